// round 10
// baseline (speedup 1.0000x reference)
#include <cuda_runtime.h>
#include <cuda_bf16.h>
#include <cstdint>

#define NN 100000
#define NE 1600000

typedef unsigned long long ull;

// ---------------------------------------------------------------------------
// Device scratch (no runtime allocation allowed)
// ---------------------------------------------------------------------------
__device__ float g_SR[(size_t)NN * 256];   // [n][0:128]=S(+b1), [128:256]=R
__device__ float g_deg[NN];                // degree, then 1/max(deg,1)
__device__ ull   g_W1f[16 * 2 * 2 * 32];   // B1 frags: [j16][t2][term2][lane32]
__device__ ull   g_W2f[8 * 8 * 2 * 32];    // B2 frags: [j8][t8][term2][lane32]

// ---------------------------------------------------------------------------
// helpers
// ---------------------------------------------------------------------------
__device__ __forceinline__ void mma16816(float c[4], const uint32_t a[4],
                                         uint32_t b0, uint32_t b1) {
    asm volatile(
        "mma.sync.aligned.m16n8k16.row.col.f32.bf16.bf16.f32 "
        "{%0,%1,%2,%3},{%4,%5,%6,%7},{%8,%9},{%0,%1,%2,%3};"
        : "+f"(c[0]), "+f"(c[1]), "+f"(c[2]), "+f"(c[3])
        : "r"(a[0]), "r"(a[1]), "r"(a[2]), "r"(a[3]), "r"(b0), "r"(b1));
}

// pack (x -> low half, y -> high half) as bf16x2; also produce residual pack
__device__ __forceinline__ void bfs2(float x, float y, uint32_t& hi, uint32_t& lo) {
    asm("cvt.rn.bf16x2.f32 %0, %1, %2;" : "=r"(hi) : "f"(y), "f"(x));
    float xr = x - __uint_as_float(hi << 16);
    float yr = y - __uint_as_float(hi & 0xFFFF0000u);
    asm("cvt.rn.bf16x2.f32 %0, %1, %2;" : "=r"(lo) : "f"(yr), "f"(xr));
}

// fp32x2 helpers for node-side kernels
__device__ __forceinline__ ull dup2(float x) { ull r; asm("mov.b64 %0,{%1,%1};" : "=l"(r) : "f"(x)); return r; }
__device__ __forceinline__ float2 up2(ull v) { float2 r; asm("mov.b64 {%0,%1},%2;" : "=f"(r.x), "=f"(r.y) : "l"(v)); return r; }
__device__ __forceinline__ ull fma2(ull a, ull b, ull c) { ull d; asm("fma.rn.f32x2 %0,%1,%2,%3;" : "=l"(d) : "l"(a), "l"(b), "l"(c)); return d; }

// ---------------------------------------------------------------------------
// Degree kernels (R7-proven pipeline)
// ---------------------------------------------------------------------------
__global__ void zero_deg_kernel() {
    int i = blockIdx.x * blockDim.x + threadIdx.x;
    if (i < NN) g_deg[i] = 0.0f;
}
__global__ void deg_kernel(const int* __restrict__ recv) {
    int e = blockIdx.x * blockDim.x + threadIdx.x;
    if (e < NE) atomicAdd(&g_deg[recv[e]], 1.0f);
}
__global__ void invdeg_kernel() {
    int i = blockIdx.x * blockDim.x + threadIdx.x;
    if (i < NN) g_deg[i] = 1.0f / fmaxf(g_deg[i], 1.0f);
}

// ---------------------------------------------------------------------------
// Weight fragment prep (bf16 hi/lo split, mma B-fragment order)
// ---------------------------------------------------------------------------
__global__ void prep_frags(const float* __restrict__ W1, const float* __restrict__ W2) {
    int idx = blockIdx.x * blockDim.x + threadIdx.x;
    if (idx < 2048) {                        // W1c frags
        int lane = idx & 31, fragid = idx >> 5;
        int term = fragid & 1, t = (fragid >> 1) & 1, j = fragid >> 2;
        int n = j * 8 + (lane >> 2);
        int k0 = t * 16 + (lane & 3) * 2;
        float v00 = W1[(size_t)(128 + k0) * 128 + n];
        float v01 = W1[(size_t)(128 + k0 + 1) * 128 + n];
        float v10 = W1[(size_t)(128 + k0 + 8) * 128 + n];
        float v11 = W1[(size_t)(128 + k0 + 9) * 128 + n];
        uint32_t h0, l0, h1, l1;
        bfs2(v00, v01, h0, l0);
        bfs2(v10, v11, h1, l1);
        g_W1f[idx] = term ? (((ull)l1 << 32) | l0) : (((ull)h1 << 32) | h0);
    }
    if (idx < 4096) {                        // W2 frags
        int lane = idx & 31, fragid = idx >> 5;
        int term = fragid & 1, t = (fragid >> 1) & 7, j = fragid >> 4;
        int n = j * 8 + (lane >> 2);
        int k0 = t * 16 + (lane & 3) * 2;
        float v00 = W2[(size_t)k0 * 64 + n];
        float v01 = W2[(size_t)(k0 + 1) * 64 + n];
        float v10 = W2[(size_t)(k0 + 8) * 64 + n];
        float v11 = W2[(size_t)(k0 + 9) * 64 + n];
        uint32_t h0, l0, h1, l1;
        bfs2(v00, v01, h0, l0);
        bfs2(v10, v11, h1, l1);
        g_W2f[idx] = term ? (((ull)l1 << 32) | l0) : (((ull)h1 << 32) | h0);
    }
}

// ---------------------------------------------------------------------------
// Fused S|R precompute (proven): g_SR = nodes @ [W1a|W1b] (+b1 on S half)
// ---------------------------------------------------------------------------
__global__ void __launch_bounds__(256) sr_gemm_kernel(
    const float* __restrict__ A, const float* __restrict__ W1,
    const float* __restrict__ b1, int M)
{
    extern __shared__ float sm[];
    float* sAT = sm;               // [64][68]
    float* sB  = sm + 64 * 68;     // [64][256]
    const int tid = threadIdx.x;
    const int n0  = blockIdx.x * 64;

#pragma unroll
    for (int j = 0; j < 4; j++) {
        int s = tid + j * 256;
        int row = s >> 4, k0 = (s & 15) << 2, gn = n0 + row;
        float4 v = make_float4(0.f, 0.f, 0.f, 0.f);
        if (gn < M) v = *(const float4*)(A + (size_t)gn * 64 + k0);
        sAT[(k0 + 0) * 68 + row] = v.x; sAT[(k0 + 1) * 68 + row] = v.y;
        sAT[(k0 + 2) * 68 + row] = v.z; sAT[(k0 + 3) * 68 + row] = v.w;
    }
#pragma unroll
    for (int j = 0; j < 16; j++) {
        int s = tid + j * 256;
        int r = s >> 6, c4 = (s & 63) * 4;
        const float* src = (c4 < 128) ? (W1 + (size_t)r * 128 + c4)
                                      : (W1 + (size_t)(64 + r) * 128 + (c4 - 128));
        *(float4*)(sB + r * 256 + c4) = *(const float4*)src;
    }
    __syncthreads();

    const int ty = tid >> 4, tx = tid & 15;
    ull acc[4][4][2];
#pragma unroll
    for (int m = 0; m < 4; m++)
#pragma unroll
        for (int q = 0; q < 4; q++) { acc[m][q][0] = 0ull; acc[m][q][1] = 0ull; }

#pragma unroll 8
    for (int k = 0; k < 64; k++) {
        float4 a = *(const float4*)(sAT + k * 68 + ty * 4);
        ull aa[4] = {dup2(a.x), dup2(a.y), dup2(a.z), dup2(a.w)};
#pragma unroll
        for (int q = 0; q < 4; q++) {
            ulonglong2 b = *(const ulonglong2*)(sB + k * 256 + q * 64 + tx * 4);
#pragma unroll
            for (int m = 0; m < 4; m++) {
                acc[m][q][0] = fma2(aa[m], b.x, acc[m][q][0]);
                acc[m][q][1] = fma2(aa[m], b.y, acc[m][q][1]);
            }
        }
    }
    float4 bq[4];
#pragma unroll
    for (int q = 0; q < 4; q++)
        bq[q] = (q < 2) ? *(const float4*)(b1 + q * 64 + tx * 4)
                        : make_float4(0.f, 0.f, 0.f, 0.f);
#pragma unroll
    for (int m = 0; m < 4; m++) {
        int gn = n0 + ty * 4 + m;
        if (gn < M) {
#pragma unroll
            for (int q = 0; q < 4; q++) {
                float2 u0 = up2(acc[m][q][0]), u1 = up2(acc[m][q][1]);
                *(float4*)(g_SR + (size_t)gn * 256 + q * 64 + tx * 4) =
                    make_float4(u0.x + bq[q].x, u0.y + bq[q].y, u1.x + bq[q].z, u1.y + bq[q].w);
            }
        }
    }
}

// ---------------------------------------------------------------------------
// Node residual GEMM: out = nodes @ Wn + bn   (runs BEFORE edge kernel)
// ---------------------------------------------------------------------------
__global__ void __launch_bounds__(256) node_gemm_small(
    const float* __restrict__ A, const float* __restrict__ B,
    const float* __restrict__ bias, float* __restrict__ C, int M)
{
    extern __shared__ float sm[];
    float* sAT = sm;
    float* sB  = sm + 64 * 68;
    const int tid = threadIdx.x;
    const int n0  = blockIdx.x * 64;

#pragma unroll
    for (int j = 0; j < 4; j++) {
        int s = tid + j * 256;
        int row = s >> 4, k0 = (s & 15) << 2, gn = n0 + row;
        float4 v = make_float4(0.f, 0.f, 0.f, 0.f);
        if (gn < M) v = *(const float4*)(A + (size_t)gn * 64 + k0);
        sAT[(k0 + 0) * 68 + row] = v.x; sAT[(k0 + 1) * 68 + row] = v.y;
        sAT[(k0 + 2) * 68 + row] = v.z; sAT[(k0 + 3) * 68 + row] = v.w;
    }
#pragma unroll
    for (int j = 0; j < 4; j++) {
        int s = tid + j * 256;
        ((float4*)sB)[s] = ((const float4*)B)[s];
    }
    __syncthreads();

    const int ty = tid >> 4, tx = tid & 15;
    ull acc[4][2];
#pragma unroll
    for (int m = 0; m < 4; m++) { acc[m][0] = 0ull; acc[m][1] = 0ull; }
#pragma unroll 8
    for (int k = 0; k < 64; k++) {
        float4 a = *(const float4*)(sAT + k * 68 + ty * 4);
        ulonglong2 b = *(const ulonglong2*)(sB + k * 64 + tx * 4);
        ull aa[4] = {dup2(a.x), dup2(a.y), dup2(a.z), dup2(a.w)};
#pragma unroll
        for (int m = 0; m < 4; m++) {
            acc[m][0] = fma2(aa[m], b.x, acc[m][0]);
            acc[m][1] = fma2(aa[m], b.y, acc[m][1]);
        }
    }
    float4 bb = *(const float4*)(bias + tx * 4);
#pragma unroll
    for (int m = 0; m < 4; m++) {
        int gn = n0 + ty * 4 + m;
        if (gn < M) {
            float2 u0 = up2(acc[m][0]), u1 = up2(acc[m][1]);
            *(float4*)(C + (size_t)gn * 64 + tx * 4) =
                make_float4(u0.x + bb.x, u0.y + bb.y, u1.x + bb.z, u1.y + bb.w);
        }
    }
}

// ---------------------------------------------------------------------------
// Edge kernel: persistent warps, mma.sync bf16x3, GEMM2 interleaved into the
// t2 loop so A2 fragments never persist (c2-all-j accumulators instead).
// Register peak ~130 -> 3 blocks/SM (12 warps). Pipeline identical to R7:
// reads invdeg, scatters scaled (m+b2)*invd.
// ---------------------------------------------------------------------------
#define N_CHUNKS (NE / 32)

__global__ void __launch_bounds__(128, 3) edge_kernel(
    const float* __restrict__ edges,
    const int*   __restrict__ senders,
    const int*   __restrict__ receivers,
    const float* __restrict__ b2,
    float*       __restrict__ out)
{
    extern __shared__ char smem[];
    ull*   sW1f = (ull*)smem;
    ull*   sW2f = (ull*)(smem + 16384);
    float* sE   = (float*)(smem + 49152);

    const int tid  = threadIdx.x;
    const int w    = tid >> 5;
    const int lane = tid & 31;

    // stage weight fragments once per block
#pragma unroll
    for (int j = 0; j < 16; j++) sW1f[tid + j * 128] = g_W1f[tid + j * 128];
#pragma unroll
    for (int j = 0; j < 32; j++) sW2f[tid + j * 128] = g_W2f[tid + j * 128];
    __syncthreads();

    float* myE = sE + w * 32 * 36;
    const int gw     = blockIdx.x * 4 + w;
    const int stride = gridDim.x * 4;

    const int r   = lane >> 2;          // 0..7
    const int c2x = (lane & 3) * 2;     // 0,2,4,6
    const int pb  = (lane >> 1) & 1;    // pair base selector
    const bool oddl = lane & 1;

    for (int chunk = gw; chunk < N_CHUNKS; chunk += stride) {
        const int e0 = chunk * 32;
        __syncwarp();
#pragma unroll
        for (int q = 0; q < 8; q++) {
            int row = q * 4 + (lane >> 3);
            int col = (lane & 7) * 4;
            *(float4*)(myE + row * 36 + col) =
                *(const float4*)(edges + (size_t)(e0 + row) * 32 + col);
        }
        const int snd = senders[e0 + lane];
        const int rcv = receivers[e0 + lane];
        const float ivl = g_deg[rcv];
        __syncwarp();

#pragma unroll
        for (int mt = 0; mt < 2; mt++) {
            const int mb = mt * 16;

            // ---- A1 fragments (edge feats, hi/lo split) ----
            uint32_t a1h[2][4], a1l[2][4];
#pragma unroll
            for (int t = 0; t < 2; t++) {
                float2 x0 = *(const float2*)(myE + (mb + r) * 36 + t * 16 + c2x);
                float2 x1 = *(const float2*)(myE + (mb + r + 8) * 36 + t * 16 + c2x);
                float2 x2 = *(const float2*)(myE + (mb + r) * 36 + t * 16 + c2x + 8);
                float2 x3 = *(const float2*)(myE + (mb + r + 8) * 36 + t * 16 + c2x + 8);
                bfs2(x0.x, x0.y, a1h[t][0], a1l[t][0]);
                bfs2(x1.x, x1.y, a1h[t][1], a1l[t][1]);
                bfs2(x2.x, x2.y, a1h[t][2], a1l[t][2]);
                bfs2(x3.x, x3.y, a1h[t][3], a1l[t][3]);
            }

            const int s_r  = __shfl_sync(0xFFFFFFFFu, snd, mb + r);
            const int s_r8 = __shfl_sync(0xFFFFFFFFu, snd, mb + r + 8);
            const int r_r  = __shfl_sync(0xFFFFFFFFu, rcv, mb + r);
            const int r_r8 = __shfl_sync(0xFFFFFFFFu, rcv, mb + r + 8);
            const float* Sr  = g_SR + (size_t)s_r  * 256;
            const float* Sr8 = g_SR + (size_t)s_r8 * 256;
            const float* Rr  = g_SR + (size_t)r_r  * 256 + 128;
            const float* Rr8 = g_SR + (size_t)r_r8 * 256 + 128;

            // all-j GEMM2 accumulators (replaces resident A2 fragments)
            float c2[8][4];
#pragma unroll
            for (int j = 0; j < 8; j++)
#pragma unroll
                for (int v = 0; v < 4; v++) c2[j][v] = 0.f;

            // ---- fused GEMM1 -> epilogue1 -> GEMM2 (per k-step t2) ----
#pragma unroll
            for (int t2 = 0; t2 < 8; t2++) {
                float c1[2][4] = {{0.f, 0.f, 0.f, 0.f}, {0.f, 0.f, 0.f, 0.f}};
#pragma unroll
                for (int half = 0; half < 2; half++) {
                    int j = t2 * 2 + half;
#pragma unroll
                    for (int t = 0; t < 2; t++) {
                        ull bh = sW1f[((j * 2 + t) * 2 + 0) * 32 + lane];
                        ull bl = sW1f[((j * 2 + t) * 2 + 1) * 32 + lane];
                        uint32_t bh0 = (uint32_t)bh, bh1 = (uint32_t)(bh >> 32);
                        uint32_t bl0 = (uint32_t)bl, bl1 = (uint32_t)(bl >> 32);
                        mma16816(c1[half], a1h[t], bh0, bh1);
                        mma16816(c1[half], a1h[t], bl0, bl1);
                        mma16816(c1[half], a1l[t], bh0, bh1);
                    }
                }
                // epilogue1: h = relu(c1 + S + R), split -> transient A2 frag
                uint32_t a2h[4], a2l[4];
#pragma unroll
                for (int half = 0; half < 2; half++) {
                    int j = t2 * 2 + half;
                    float2 sv0 = *(const float2*)(Sr  + j * 8 + c2x);
                    float2 sv1 = *(const float2*)(Sr8 + j * 8 + c2x);
                    float2 rv0 = *(const float2*)(Rr  + j * 8 + c2x);
                    float2 rv1 = *(const float2*)(Rr8 + j * 8 + c2x);
                    float h0 = fmaxf(c1[half][0] + sv0.x + rv0.x, 0.f);
                    float h1 = fmaxf(c1[half][1] + sv0.y + rv0.y, 0.f);
                    float h2 = fmaxf(c1[half][2] + sv1.x + rv1.x, 0.f);
                    float h3 = fmaxf(c1[half][3] + sv1.y + rv1.y, 0.f);
                    bfs2(h0, h1, a2h[half * 2 + 0], a2l[half * 2 + 0]);
                    bfs2(h2, h3, a2h[half * 2 + 1], a2l[half * 2 + 1]);
                }
                // GEMM2 for this k-step: consume A2 frag immediately
#pragma unroll
                for (int j = 0; j < 8; j++) {
                    ull bh = sW2f[((j * 8 + t2) * 2 + 0) * 32 + lane];
                    ull bl = sW2f[((j * 8 + t2) * 2 + 1) * 32 + lane];
                    uint32_t bh0 = (uint32_t)bh, bh1 = (uint32_t)(bh >> 32);
                    uint32_t bl0 = (uint32_t)bl, bl1 = (uint32_t)(bl >> 32);
                    mma16816(c2[j], a2h, bh0, bh1);
                    mma16816(c2[j], a2h, bl0, bl1);
                    mma16816(c2[j], a2l, bh0, bh1);
                }
            }

            // ---- epilogue2: scale by invdeg + vector-red scatter ----
            const float iv_e = __shfl_sync(0xFFFFFFFFu, ivl, mb + r);
            const float iv_o = __shfl_sync(0xFFFFFFFFu, ivl, mb + r + 8);
            const int   er   = oddl ? r_r8 : r_r;
            const float iv   = oddl ? iv_o : iv_e;
            float* outp = out + (size_t)er * 64 + pb * 4;

#pragma unroll
            for (int j = 0; j < 8; j++) {
                float x0 = __shfl_xor_sync(0xFFFFFFFFu, c2[j][0], 1);
                float x1 = __shfl_xor_sync(0xFFFFFFFFu, c2[j][1], 1);
                float x2 = __shfl_xor_sync(0xFFFFFFFFu, c2[j][2], 1);
                float x3 = __shfl_xor_sync(0xFFFFFFFFu, c2[j][3], 1);
                float v0, v1, v2, v3;
                if (!oddl) { v0 = c2[j][0]; v1 = c2[j][1]; v2 = x0; v3 = x1; }
                else       { v0 = x2;       v1 = x3;       v2 = c2[j][2]; v3 = c2[j][3]; }
                float4 bb = *(const float4*)(b2 + j * 8 + pb * 4);
                v0 = (v0 + bb.x) * iv;  v1 = (v1 + bb.y) * iv;
                v2 = (v2 + bb.z) * iv;  v3 = (v3 + bb.w) * iv;
                asm volatile("red.global.add.v4.f32 [%0], {%1,%2,%3,%4};"
                             :: "l"(outp + j * 8), "f"(v0), "f"(v1), "f"(v2), "f"(v3)
                             : "memory");
            }
        }
    }
}

// ---------------------------------------------------------------------------
// Launch (R7-proven pipeline)
// ---------------------------------------------------------------------------
extern "C" void kernel_launch(void* const* d_in, const int* in_sizes, int n_in,
                              void* d_out, int out_size)
{
    const float* nodes     = (const float*)d_in[0];
    const float* edges     = (const float*)d_in[1];
    const int*   senders   = (const int*)d_in[2];
    const int*   receivers = (const int*)d_in[3];
    const float* W1        = (const float*)d_in[4];
    const float* b1        = (const float*)d_in[5];
    const float* W2        = (const float*)d_in[6];
    const float* b2        = (const float*)d_in[7];
    const float* Wn        = (const float*)d_in[8];
    const float* bn        = (const float*)d_in[9];
    float* out = (float*)d_out;

    const size_t sm_sr    = (64 * 68 + 64 * 256) * sizeof(float);
    const size_t sm_small = (64 * 68 + 64 * 64) * sizeof(float);
    const size_t sm_edge  = 16384 + 32768 + 4 * 32 * 36 * sizeof(float);  // 67,584

    cudaFuncSetAttribute(sr_gemm_kernel,
                         cudaFuncAttributeMaxDynamicSharedMemorySize, (int)sm_sr);
    cudaFuncSetAttribute(edge_kernel,
                         cudaFuncAttributeMaxDynamicSharedMemorySize, (int)sm_edge);

    zero_deg_kernel<<<(NN + 255) / 256, 256>>>();
    deg_kernel<<<(NE + 255) / 256, 256>>>(receivers);
    invdeg_kernel<<<(NN + 255) / 256, 256>>>();

    prep_frags<<<16, 256>>>(W1, W2);

    int gnodes = (NN + 63) / 64;
    sr_gemm_kernel<<<gnodes, 256, sm_sr>>>(nodes, W1, b1, NN);
    node_gemm_small<<<gnodes, 256, sm_small>>>(nodes, Wn, bn, out, NN);

    edge_kernel<<<444, 128, sm_edge>>>(edges, senders, receivers, b2, out);
}

// round 11
// speedup vs baseline: 1.6690x; 1.6690x over previous
#include <cuda_runtime.h>
#include <cuda_bf16.h>
#include <cstdint>

#define NN 100000
#define NE 1600000

typedef unsigned long long ull;

// ---------------------------------------------------------------------------
// Device scratch (no runtime allocation allowed)
// ---------------------------------------------------------------------------
__device__ float g_SR[(size_t)NN * 256];   // [n][0:128]=S(+b1), [128:256]=R
__device__ float g_deg[NN];                // degree, then 1/max(deg,1)
__device__ ull   g_W1f[16 * 2 * 2 * 32];   // B1 frags: [j16][t2][term2][lane32]
__device__ ull   g_W2f[8 * 8 * 2 * 32];    // B2 frags: [j8][t8][term2][lane32]

// ---------------------------------------------------------------------------
// helpers
// ---------------------------------------------------------------------------
__device__ __forceinline__ void mma16816(float c[4], const uint32_t a[4],
                                         uint32_t b0, uint32_t b1) {
    asm volatile(
        "mma.sync.aligned.m16n8k16.row.col.f32.bf16.bf16.f32 "
        "{%0,%1,%2,%3},{%4,%5,%6,%7},{%8,%9},{%0,%1,%2,%3};"
        : "+f"(c[0]), "+f"(c[1]), "+f"(c[2]), "+f"(c[3])
        : "r"(a[0]), "r"(a[1]), "r"(a[2]), "r"(a[3]), "r"(b0), "r"(b1));
}

// pack (x -> low half, y -> high half) as bf16x2; also produce residual pack
__device__ __forceinline__ void bfs2(float x, float y, uint32_t& hi, uint32_t& lo) {
    asm("cvt.rn.bf16x2.f32 %0, %1, %2;" : "=r"(hi) : "f"(y), "f"(x));
    float xr = x - __uint_as_float(hi << 16);
    float yr = y - __uint_as_float(hi & 0xFFFF0000u);
    asm("cvt.rn.bf16x2.f32 %0, %1, %2;" : "=r"(lo) : "f"(yr), "f"(xr));
}

// fp32x2 helpers for node-side kernels
__device__ __forceinline__ ull dup2(float x) { ull r; asm("mov.b64 %0,{%1,%1};" : "=l"(r) : "f"(x)); return r; }
__device__ __forceinline__ float2 up2(ull v) { float2 r; asm("mov.b64 {%0,%1},%2;" : "=f"(r.x), "=f"(r.y) : "l"(v)); return r; }
__device__ __forceinline__ ull fma2(ull a, ull b, ull c) { ull d; asm("fma.rn.f32x2 %0,%1,%2,%3;" : "=l"(d) : "l"(a), "l"(b), "l"(c)); return d; }

// ---------------------------------------------------------------------------
// Merged init kernel: zero g_deg + build weight fragments
// ---------------------------------------------------------------------------
__global__ void init_kernel(const float* __restrict__ W1, const float* __restrict__ W2) {
    int idx = blockIdx.x * blockDim.x + threadIdx.x;
    if (idx < NN) g_deg[idx] = 0.0f;
    if (idx < 2048) {                        // W1c frags
        int lane = idx & 31, fragid = idx >> 5;
        int term = fragid & 1, t = (fragid >> 1) & 1, j = fragid >> 2;
        int n = j * 8 + (lane >> 2);
        int k0 = t * 16 + (lane & 3) * 2;
        float v00 = W1[(size_t)(128 + k0) * 128 + n];
        float v01 = W1[(size_t)(128 + k0 + 1) * 128 + n];
        float v10 = W1[(size_t)(128 + k0 + 8) * 128 + n];
        float v11 = W1[(size_t)(128 + k0 + 9) * 128 + n];
        uint32_t h0, l0, h1, l1;
        bfs2(v00, v01, h0, l0);
        bfs2(v10, v11, h1, l1);
        g_W1f[idx] = term ? (((ull)l1 << 32) | l0) : (((ull)h1 << 32) | h0);
    }
    if (idx < 4096) {                        // W2 frags
        int lane = idx & 31, fragid = idx >> 5;
        int term = fragid & 1, t = (fragid >> 1) & 7, j = fragid >> 4;
        int n = j * 8 + (lane >> 2);
        int k0 = t * 16 + (lane & 3) * 2;
        float v00 = W2[(size_t)k0 * 64 + n];
        float v01 = W2[(size_t)(k0 + 1) * 64 + n];
        float v10 = W2[(size_t)(k0 + 8) * 64 + n];
        float v11 = W2[(size_t)(k0 + 9) * 64 + n];
        uint32_t h0, l0, h1, l1;
        bfs2(v00, v01, h0, l0);
        bfs2(v10, v11, h1, l1);
        g_W2f[idx] = term ? (((ull)l1 << 32) | l0) : (((ull)h1 << 32) | h0);
    }
}

// ---------------------------------------------------------------------------
// Vectorized degree kernel: int4 loads, 4 REDs per thread
// ---------------------------------------------------------------------------
__global__ void deg_kernel_v4(const int* __restrict__ recv) {
    int i = blockIdx.x * blockDim.x + threadIdx.x;
    if (i < NE / 4) {
        int4 r4 = ((const int4*)recv)[i];
        atomicAdd(&g_deg[r4.x], 1.0f);
        atomicAdd(&g_deg[r4.y], 1.0f);
        atomicAdd(&g_deg[r4.z], 1.0f);
        atomicAdd(&g_deg[r4.w], 1.0f);
    }
}

// ---------------------------------------------------------------------------
// Fused node kernel: one pass over nodes computes
//   g_SR[M,256] = nodes @ [W1a|W1b] (+b1 on S half)
//   out[M,64]   = nodes @ Wn + bn
//   g_deg       -> 1/max(deg,1)   (folded in)
// B tile is 320 cols: [0:128)=W1a, [128:256)=W1b, [256:320)=Wn
// ---------------------------------------------------------------------------
__global__ void __launch_bounds__(256) node_kernel(
    const float* __restrict__ A, const float* __restrict__ W1,
    const float* __restrict__ Wn, const float* __restrict__ b1,
    const float* __restrict__ bn, float* __restrict__ out, int M)
{
    extern __shared__ float sm[];
    float* sAT = sm;               // [64][68]
    float* sB  = sm + 64 * 68;     // [64][320]
    const int tid = threadIdx.x;
    const int n0  = blockIdx.x * 64;

    // invdeg for this block's rows
    if (tid < 64 && n0 + tid < M)
        g_deg[n0 + tid] = 1.0f / fmaxf(g_deg[n0 + tid], 1.0f);

#pragma unroll
    for (int j = 0; j < 4; j++) {
        int s = tid + j * 256;
        int row = s >> 4, k0 = (s & 15) << 2, gn = n0 + row;
        float4 v = make_float4(0.f, 0.f, 0.f, 0.f);
        if (gn < M) v = *(const float4*)(A + (size_t)gn * 64 + k0);
        sAT[(k0 + 0) * 68 + row] = v.x; sAT[(k0 + 1) * 68 + row] = v.y;
        sAT[(k0 + 2) * 68 + row] = v.z; sAT[(k0 + 3) * 68 + row] = v.w;
    }
    // B tile: 64 rows x 80 float4
#pragma unroll
    for (int j = 0; j < 20; j++) {
        int s  = tid + j * 256;
        int r  = s / 80;
        int c4 = (s % 80) * 4;
        const float* src;
        if (c4 < 128)       src = W1 + (size_t)r * 128 + c4;
        else if (c4 < 256)  src = W1 + (size_t)(64 + r) * 128 + (c4 - 128);
        else                src = Wn + (size_t)r * 64 + (c4 - 256);
        *(float4*)(sB + r * 320 + c4) = *(const float4*)src;
    }
    __syncthreads();

    const int ty = tid >> 4, tx = tid & 15;
    ull acc[4][5][2];
#pragma unroll
    for (int m = 0; m < 4; m++)
#pragma unroll
        for (int q = 0; q < 5; q++) { acc[m][q][0] = 0ull; acc[m][q][1] = 0ull; }

#pragma unroll 4
    for (int k = 0; k < 64; k++) {
        float4 a = *(const float4*)(sAT + k * 68 + ty * 4);
        ull aa[4] = {dup2(a.x), dup2(a.y), dup2(a.z), dup2(a.w)};
#pragma unroll
        for (int q = 0; q < 5; q++) {
            ulonglong2 b = *(const ulonglong2*)(sB + k * 320 + q * 64 + tx * 4);
#pragma unroll
            for (int m = 0; m < 4; m++) {
                acc[m][q][0] = fma2(aa[m], b.x, acc[m][q][0]);
                acc[m][q][1] = fma2(aa[m], b.y, acc[m][q][1]);
            }
        }
    }
    float4 bq[5];
#pragma unroll
    for (int q = 0; q < 5; q++) {
        if (q < 2)      bq[q] = *(const float4*)(b1 + q * 64 + tx * 4);
        else if (q < 4) bq[q] = make_float4(0.f, 0.f, 0.f, 0.f);
        else            bq[q] = *(const float4*)(bn + tx * 4);
    }
#pragma unroll
    for (int m = 0; m < 4; m++) {
        int gn = n0 + ty * 4 + m;
        if (gn < M) {
#pragma unroll
            for (int q = 0; q < 4; q++) {
                float2 u0 = up2(acc[m][q][0]), u1 = up2(acc[m][q][1]);
                *(float4*)(g_SR + (size_t)gn * 256 + q * 64 + tx * 4) =
                    make_float4(u0.x + bq[q].x, u0.y + bq[q].y, u1.x + bq[q].z, u1.y + bq[q].w);
            }
            float2 u0 = up2(acc[m][4][0]), u1 = up2(acc[m][4][1]);
            *(float4*)(out + (size_t)gn * 64 + tx * 4) =
                make_float4(u0.x + bq[4].x, u0.y + bq[4].y, u1.x + bq[4].z, u1.y + bq[4].w);
        }
    }
}

// ---------------------------------------------------------------------------
// Edge kernel: EXACT R7 configuration (measured 869us total).
// persistent warps, mma.sync bf16x3, register-resident fusion,
// 128 threads, 2 blocks/SM, grid 304.
// ---------------------------------------------------------------------------
#define N_CHUNKS (NE / 32)

__global__ void __launch_bounds__(128, 2) edge_kernel(
    const float* __restrict__ edges,
    const int*   __restrict__ senders,
    const int*   __restrict__ receivers,
    const float* __restrict__ b2,
    float*       __restrict__ out)
{
    extern __shared__ char smem[];
    ull*   sW1f = (ull*)smem;
    ull*   sW2f = (ull*)(smem + 16384);
    float* sE   = (float*)(smem + 49152);

    const int tid  = threadIdx.x;
    const int w    = tid >> 5;
    const int lane = tid & 31;

    // stage weight fragments once per block
#pragma unroll
    for (int j = 0; j < 16; j++) sW1f[tid + j * 128] = g_W1f[tid + j * 128];
#pragma unroll
    for (int j = 0; j < 32; j++) sW2f[tid + j * 128] = g_W2f[tid + j * 128];
    __syncthreads();

    float* myE = sE + w * 32 * 36;
    const int gw     = blockIdx.x * 4 + w;
    const int stride = gridDim.x * 4;

    const int r   = lane >> 2;          // 0..7
    const int c2x = (lane & 3) * 2;     // 0,2,4,6
    const int pb  = (lane >> 1) & 1;    // pair base selector
    const bool oddl = lane & 1;

    for (int chunk = gw; chunk < N_CHUNKS; chunk += stride) {
        const int e0 = chunk * 32;
        __syncwarp();
#pragma unroll
        for (int q = 0; q < 8; q++) {
            int row = q * 4 + (lane >> 3);
            int col = (lane & 7) * 4;
            *(float4*)(myE + row * 36 + col) =
                *(const float4*)(edges + (size_t)(e0 + row) * 32 + col);
        }
        const int snd = senders[e0 + lane];
        const int rcv = receivers[e0 + lane];
        const float ivl = g_deg[rcv];
        __syncwarp();

#pragma unroll
        for (int mt = 0; mt < 2; mt++) {
            const int mb = mt * 16;

            // ---- A1 fragments (edge feats, hi/lo split) ----
            uint32_t a1h[2][4], a1l[2][4];
#pragma unroll
            for (int t = 0; t < 2; t++) {
                float2 x0 = *(const float2*)(myE + (mb + r) * 36 + t * 16 + c2x);
                float2 x1 = *(const float2*)(myE + (mb + r + 8) * 36 + t * 16 + c2x);
                float2 x2 = *(const float2*)(myE + (mb + r) * 36 + t * 16 + c2x + 8);
                float2 x3 = *(const float2*)(myE + (mb + r + 8) * 36 + t * 16 + c2x + 8);
                bfs2(x0.x, x0.y, a1h[t][0], a1l[t][0]);
                bfs2(x1.x, x1.y, a1h[t][1], a1l[t][1]);
                bfs2(x2.x, x2.y, a1h[t][2], a1l[t][2]);
                bfs2(x3.x, x3.y, a1h[t][3], a1l[t][3]);
            }

            const int s_r  = __shfl_sync(0xFFFFFFFFu, snd, mb + r);
            const int s_r8 = __shfl_sync(0xFFFFFFFFu, snd, mb + r + 8);
            const int r_r  = __shfl_sync(0xFFFFFFFFu, rcv, mb + r);
            const int r_r8 = __shfl_sync(0xFFFFFFFFu, rcv, mb + r + 8);
            const float* Sr  = g_SR + (size_t)s_r  * 256;
            const float* Sr8 = g_SR + (size_t)s_r8 * 256;
            const float* Rr  = g_SR + (size_t)r_r  * 256 + 128;
            const float* Rr8 = g_SR + (size_t)r_r8 * 256 + 128;

            // ---- GEMM1 + epilogue1 -> A2 frags ----
            uint32_t a2h[8][4], a2l[8][4];
#pragma unroll
            for (int t2 = 0; t2 < 8; t2++) {
                float c1[2][4] = {{0.f, 0.f, 0.f, 0.f}, {0.f, 0.f, 0.f, 0.f}};
#pragma unroll
                for (int half = 0; half < 2; half++) {
                    int j = t2 * 2 + half;
#pragma unroll
                    for (int t = 0; t < 2; t++) {
                        ull bh = sW1f[((j * 2 + t) * 2 + 0) * 32 + lane];
                        ull bl = sW1f[((j * 2 + t) * 2 + 1) * 32 + lane];
                        uint32_t bh0 = (uint32_t)bh, bh1 = (uint32_t)(bh >> 32);
                        uint32_t bl0 = (uint32_t)bl, bl1 = (uint32_t)(bl >> 32);
                        mma16816(c1[half], a1h[t], bh0, bh1);
                        mma16816(c1[half], a1h[t], bl0, bl1);
                        mma16816(c1[half], a1l[t], bh0, bh1);
                    }
                }
#pragma unroll
                for (int half = 0; half < 2; half++) {
                    int j = t2 * 2 + half;
                    float2 sv0 = *(const float2*)(Sr  + j * 8 + c2x);
                    float2 sv1 = *(const float2*)(Sr8 + j * 8 + c2x);
                    float2 rv0 = *(const float2*)(Rr  + j * 8 + c2x);
                    float2 rv1 = *(const float2*)(Rr8 + j * 8 + c2x);
                    float h0 = fmaxf(c1[half][0] + sv0.x + rv0.x, 0.f);
                    float h1 = fmaxf(c1[half][1] + sv0.y + rv0.y, 0.f);
                    float h2 = fmaxf(c1[half][2] + sv1.x + rv1.x, 0.f);
                    float h3 = fmaxf(c1[half][3] + sv1.y + rv1.y, 0.f);
                    bfs2(h0, h1, a2h[t2][half * 2 + 0], a2l[t2][half * 2 + 0]);
                    bfs2(h2, h3, a2h[t2][half * 2 + 1], a2l[t2][half * 2 + 1]);
                }
            }

            const float iv_e = __shfl_sync(0xFFFFFFFFu, ivl, mb + r);
            const float iv_o = __shfl_sync(0xFFFFFFFFu, ivl, mb + r + 8);
            const int   er   = oddl ? r_r8 : r_r;
            const float iv   = oddl ? iv_o : iv_e;
            float* outp = out + (size_t)er * 64 + pb * 4;

            // ---- GEMM2 per n-tile + epilogue2 scatter ----
#pragma unroll
            for (int j = 0; j < 8; j++) {
                float c2[4] = {0.f, 0.f, 0.f, 0.f};
#pragma unroll
                for (int t = 0; t < 8; t++) {
                    ull bh = sW2f[((j * 8 + t) * 2 + 0) * 32 + lane];
                    ull bl = sW2f[((j * 8 + t) * 2 + 1) * 32 + lane];
                    uint32_t bh0 = (uint32_t)bh, bh1 = (uint32_t)(bh >> 32);
                    uint32_t bl0 = (uint32_t)bl, bl1 = (uint32_t)(bl >> 32);
                    mma16816(c2, a2h[t], bh0, bh1);
                    mma16816(c2, a2h[t], bl0, bl1);
                    mma16816(c2, a2l[t], bh0, bh1);
                }
                float x0 = __shfl_xor_sync(0xFFFFFFFFu, c2[0], 1);
                float x1 = __shfl_xor_sync(0xFFFFFFFFu, c2[1], 1);
                float x2 = __shfl_xor_sync(0xFFFFFFFFu, c2[2], 1);
                float x3 = __shfl_xor_sync(0xFFFFFFFFu, c2[3], 1);
                float v0, v1, v2, v3;
                if (!oddl) { v0 = c2[0]; v1 = c2[1]; v2 = x0; v3 = x1; }
                else       { v0 = x2;    v1 = x3;    v2 = c2[2]; v3 = c2[3]; }
                float4 bb = *(const float4*)(b2 + j * 8 + pb * 4);
                v0 = (v0 + bb.x) * iv;  v1 = (v1 + bb.y) * iv;
                v2 = (v2 + bb.z) * iv;  v3 = (v3 + bb.w) * iv;
                asm volatile("red.global.add.v4.f32 [%0], {%1,%2,%3,%4};"
                             :: "l"(outp + j * 8), "f"(v0), "f"(v1), "f"(v2), "f"(v3)
                             : "memory");
            }
        }
    }
}

// ---------------------------------------------------------------------------
// Launch
// ---------------------------------------------------------------------------
extern "C" void kernel_launch(void* const* d_in, const int* in_sizes, int n_in,
                              void* d_out, int out_size)
{
    const float* nodes     = (const float*)d_in[0];
    const float* edges     = (const float*)d_in[1];
    const int*   senders   = (const int*)d_in[2];
    const int*   receivers = (const int*)d_in[3];
    const float* W1        = (const float*)d_in[4];
    const float* b1        = (const float*)d_in[5];
    const float* W2        = (const float*)d_in[6];
    const float* b2        = (const float*)d_in[7];
    const float* Wn        = (const float*)d_in[8];
    const float* bn        = (const float*)d_in[9];
    float* out = (float*)d_out;

    const size_t sm_node = (64 * 68 + 64 * 320) * sizeof(float);          // 99,328 B
    const size_t sm_edge = 16384 + 32768 + 4 * 32 * 36 * sizeof(float);   // 67,584 B

    cudaFuncSetAttribute(node_kernel,
                         cudaFuncAttributeMaxDynamicSharedMemorySize, (int)sm_node);
    cudaFuncSetAttribute(edge_kernel,
                         cudaFuncAttributeMaxDynamicSharedMemorySize, (int)sm_edge);

    init_kernel<<<(NN + 255) / 256, 256>>>(W1, W2);
    deg_kernel_v4<<<(NE / 4 + 255) / 256, 256>>>(receivers);

    int gnodes = (NN + 63) / 64;
    node_kernel<<<gnodes, 256, sm_node>>>(nodes, W1, Wn, b1, bn, out, NN);

    edge_kernel<<<304, 128, sm_edge>>>(edges, senders, receivers, b2, out);
}

// round 12
// speedup vs baseline: 1.7770x; 1.0648x over previous
#include <cuda_runtime.h>
#include <cuda_bf16.h>
#include <cstdint>

#define NN 100000
#define NE 1600000

typedef unsigned long long ull;

// ---------------------------------------------------------------------------
// Device scratch (no runtime allocation allowed)
// ---------------------------------------------------------------------------
__device__ float g_SR[(size_t)NN * 256];   // [n][0:128]=S(+b1), [128:256]=R
__device__ float g_deg[NN];                // degree, then 1/max(deg,1)
__device__ ull   g_W1f[16 * 2 * 2 * 32];   // B1 frags: [j16][t2][term2][lane32]
__device__ ull   g_W2f[8 * 8 * 2 * 32];    // B2 frags: [j8][t8][term2][lane32]

// ---------------------------------------------------------------------------
// helpers
// ---------------------------------------------------------------------------
__device__ __forceinline__ void mma16816(float c[4], const uint32_t a[4],
                                         uint32_t b0, uint32_t b1) {
    asm volatile(
        "mma.sync.aligned.m16n8k16.row.col.f32.bf16.bf16.f32 "
        "{%0,%1,%2,%3},{%4,%5,%6,%7},{%8,%9},{%0,%1,%2,%3};"
        : "+f"(c[0]), "+f"(c[1]), "+f"(c[2]), "+f"(c[3])
        : "r"(a[0]), "r"(a[1]), "r"(a[2]), "r"(a[3]), "r"(b0), "r"(b1));
}

// pack (x -> low half, y -> high half) as bf16x2; also produce residual pack
__device__ __forceinline__ void bfs2(float x, float y, uint32_t& hi, uint32_t& lo) {
    asm("cvt.rn.bf16x2.f32 %0, %1, %2;" : "=r"(hi) : "f"(y), "f"(x));
    float xr = x - __uint_as_float(hi << 16);
    float yr = y - __uint_as_float(hi & 0xFFFF0000u);
    asm("cvt.rn.bf16x2.f32 %0, %1, %2;" : "=r"(lo) : "f"(yr), "f"(xr));
}

// fp32x2 helpers for node-side kernels
__device__ __forceinline__ ull dup2(float x) { ull r; asm("mov.b64 %0,{%1,%1};" : "=l"(r) : "f"(x)); return r; }
__device__ __forceinline__ float2 up2(ull v) { float2 r; asm("mov.b64 {%0,%1},%2;" : "=f"(r.x), "=f"(r.y) : "l"(v)); return r; }
__device__ __forceinline__ ull fma2(ull a, ull b, ull c) { ull d; asm("fma.rn.f32x2 %0,%1,%2,%3;" : "=l"(d) : "l"(a), "l"(b), "l"(c)); return d; }

// L2 residency helpers
__device__ __forceinline__ ull mkpol_last() {
    ull p;
    asm("createpolicy.fractional.L2::evict_last.b64 %0, 1.0;" : "=l"(p));
    return p;
}
__device__ __forceinline__ float2 ldg_keep2(const float* p, ull pol) {
    float2 v;
    asm volatile("ld.global.nc.L2::cache_hint.v2.f32 {%0,%1}, [%2], %3;"
                 : "=f"(v.x), "=f"(v.y) : "l"(p), "l"(pol));
    return v;
}
__device__ __forceinline__ void stg_keep4(float* p, float4 v, ull pol) {
    asm volatile("st.global.L2::cache_hint.v4.f32 [%0], {%1,%2,%3,%4}, %5;"
                 :: "l"(p), "f"(v.x), "f"(v.y), "f"(v.z), "f"(v.w), "l"(pol)
                 : "memory");
}

// ---------------------------------------------------------------------------
// Merged init kernel: zero g_deg + build weight fragments
// ---------------------------------------------------------------------------
__global__ void init_kernel(const float* __restrict__ W1, const float* __restrict__ W2) {
    int idx = blockIdx.x * blockDim.x + threadIdx.x;
    if (idx < NN) g_deg[idx] = 0.0f;
    if (idx < 2048) {                        // W1c frags
        int lane = idx & 31, fragid = idx >> 5;
        int term = fragid & 1, t = (fragid >> 1) & 1, j = fragid >> 2;
        int n = j * 8 + (lane >> 2);
        int k0 = t * 16 + (lane & 3) * 2;
        float v00 = W1[(size_t)(128 + k0) * 128 + n];
        float v01 = W1[(size_t)(128 + k0 + 1) * 128 + n];
        float v10 = W1[(size_t)(128 + k0 + 8) * 128 + n];
        float v11 = W1[(size_t)(128 + k0 + 9) * 128 + n];
        uint32_t h0, l0, h1, l1;
        bfs2(v00, v01, h0, l0);
        bfs2(v10, v11, h1, l1);
        g_W1f[idx] = term ? (((ull)l1 << 32) | l0) : (((ull)h1 << 32) | h0);
    }
    if (idx < 4096) {                        // W2 frags
        int lane = idx & 31, fragid = idx >> 5;
        int term = fragid & 1, t = (fragid >> 1) & 7, j = fragid >> 4;
        int n = j * 8 + (lane >> 2);
        int k0 = t * 16 + (lane & 3) * 2;
        float v00 = W2[(size_t)k0 * 64 + n];
        float v01 = W2[(size_t)(k0 + 1) * 64 + n];
        float v10 = W2[(size_t)(k0 + 8) * 64 + n];
        float v11 = W2[(size_t)(k0 + 9) * 64 + n];
        uint32_t h0, l0, h1, l1;
        bfs2(v00, v01, h0, l0);
        bfs2(v10, v11, h1, l1);
        g_W2f[idx] = term ? (((ull)l1 << 32) | l0) : (((ull)h1 << 32) | h0);
    }
}

// ---------------------------------------------------------------------------
// Vectorized degree kernel: int4 loads, 4 REDs per thread
// ---------------------------------------------------------------------------
__global__ void deg_kernel_v4(const int* __restrict__ recv) {
    int i = blockIdx.x * blockDim.x + threadIdx.x;
    if (i < NE / 4) {
        int4 r4 = __ldcs(((const int4*)recv) + i);
        atomicAdd(&g_deg[r4.x], 1.0f);
        atomicAdd(&g_deg[r4.y], 1.0f);
        atomicAdd(&g_deg[r4.z], 1.0f);
        atomicAdd(&g_deg[r4.w], 1.0f);
    }
}

// ---------------------------------------------------------------------------
// Fused node kernel: one pass over nodes computes
//   g_SR[M,256] = nodes @ [W1a|W1b] (+b1 on S half)  [stored with L2 evict_last]
//   out[M,64]   = nodes @ Wn + bn
//   g_deg       -> 1/max(deg,1)   (folded in)
// ---------------------------------------------------------------------------
__global__ void __launch_bounds__(256) node_kernel(
    const float* __restrict__ A, const float* __restrict__ W1,
    const float* __restrict__ Wn, const float* __restrict__ b1,
    const float* __restrict__ bn, float* __restrict__ out, int M)
{
    extern __shared__ float sm[];
    float* sAT = sm;               // [64][68]
    float* sB  = sm + 64 * 68;     // [64][320]
    const int tid = threadIdx.x;
    const int n0  = blockIdx.x * 64;
    const ull pol = mkpol_last();

    if (tid < 64 && n0 + tid < M)
        g_deg[n0 + tid] = 1.0f / fmaxf(g_deg[n0 + tid], 1.0f);

#pragma unroll
    for (int j = 0; j < 4; j++) {
        int s = tid + j * 256;
        int row = s >> 4, k0 = (s & 15) << 2, gn = n0 + row;
        float4 v = make_float4(0.f, 0.f, 0.f, 0.f);
        if (gn < M) v = *(const float4*)(A + (size_t)gn * 64 + k0);
        sAT[(k0 + 0) * 68 + row] = v.x; sAT[(k0 + 1) * 68 + row] = v.y;
        sAT[(k0 + 2) * 68 + row] = v.z; sAT[(k0 + 3) * 68 + row] = v.w;
    }
#pragma unroll
    for (int j = 0; j < 20; j++) {
        int s  = tid + j * 256;
        int r  = s / 80;
        int c4 = (s % 80) * 4;
        const float* src;
        if (c4 < 128)       src = W1 + (size_t)r * 128 + c4;
        else if (c4 < 256)  src = W1 + (size_t)(64 + r) * 128 + (c4 - 128);
        else                src = Wn + (size_t)r * 64 + (c4 - 256);
        *(float4*)(sB + r * 320 + c4) = *(const float4*)src;
    }
    __syncthreads();

    const int ty = tid >> 4, tx = tid & 15;
    ull acc[4][5][2];
#pragma unroll
    for (int m = 0; m < 4; m++)
#pragma unroll
        for (int q = 0; q < 5; q++) { acc[m][q][0] = 0ull; acc[m][q][1] = 0ull; }

#pragma unroll 4
    for (int k = 0; k < 64; k++) {
        float4 a = *(const float4*)(sAT + k * 68 + ty * 4);
        ull aa[4] = {dup2(a.x), dup2(a.y), dup2(a.z), dup2(a.w)};
#pragma unroll
        for (int q = 0; q < 5; q++) {
            ulonglong2 b = *(const ulonglong2*)(sB + k * 320 + q * 64 + tx * 4);
#pragma unroll
            for (int m = 0; m < 4; m++) {
                acc[m][q][0] = fma2(aa[m], b.x, acc[m][q][0]);
                acc[m][q][1] = fma2(aa[m], b.y, acc[m][q][1]);
            }
        }
    }
    float4 bq[5];
#pragma unroll
    for (int q = 0; q < 5; q++) {
        if (q < 2)      bq[q] = *(const float4*)(b1 + q * 64 + tx * 4);
        else if (q < 4) bq[q] = make_float4(0.f, 0.f, 0.f, 0.f);
        else            bq[q] = *(const float4*)(bn + tx * 4);
    }
#pragma unroll
    for (int m = 0; m < 4; m++) {
        int gn = n0 + ty * 4 + m;
        if (gn < M) {
#pragma unroll
            for (int q = 0; q < 4; q++) {
                float2 u0 = up2(acc[m][q][0]), u1 = up2(acc[m][q][1]);
                stg_keep4(g_SR + (size_t)gn * 256 + q * 64 + tx * 4,
                          make_float4(u0.x + bq[q].x, u0.y + bq[q].y,
                                      u1.x + bq[q].z, u1.y + bq[q].w), pol);
            }
            float2 u0 = up2(acc[m][4][0]), u1 = up2(acc[m][4][1]);
            *(float4*)(out + (size_t)gn * 64 + tx * 4) =
                make_float4(u0.x + bq[4].x, u0.y + bq[4].y, u1.x + bq[4].z, u1.y + bq[4].w);
        }
    }
}

// ---------------------------------------------------------------------------
// Edge kernel: R7/R11 structure; gathers use L2 evict_last, streams use __ldcs
// ---------------------------------------------------------------------------
#define N_CHUNKS (NE / 32)

__global__ void __launch_bounds__(128, 2) edge_kernel(
    const float* __restrict__ edges,
    const int*   __restrict__ senders,
    const int*   __restrict__ receivers,
    const float* __restrict__ b2,
    float*       __restrict__ out)
{
    extern __shared__ char smem[];
    ull*   sW1f = (ull*)smem;
    ull*   sW2f = (ull*)(smem + 16384);
    float* sE   = (float*)(smem + 49152);

    const int tid  = threadIdx.x;
    const int w    = tid >> 5;
    const int lane = tid & 31;
    const ull pol  = mkpol_last();

    // stage weight fragments once per block
#pragma unroll
    for (int j = 0; j < 16; j++) sW1f[tid + j * 128] = g_W1f[tid + j * 128];
#pragma unroll
    for (int j = 0; j < 32; j++) sW2f[tid + j * 128] = g_W2f[tid + j * 128];
    __syncthreads();

    float* myE = sE + w * 32 * 36;
    const int gw     = blockIdx.x * 4 + w;
    const int stride = gridDim.x * 4;

    const int r   = lane >> 2;          // 0..7
    const int c2x = (lane & 3) * 2;     // 0,2,4,6
    const int pb  = (lane >> 1) & 1;    // pair base selector
    const bool oddl = lane & 1;

    for (int chunk = gw; chunk < N_CHUNKS; chunk += stride) {
        const int e0 = chunk * 32;
        __syncwarp();
#pragma unroll
        for (int q = 0; q < 8; q++) {
            int row = q * 4 + (lane >> 3);
            int col = (lane & 7) * 4;
            *(float4*)(myE + row * 36 + col) =
                __ldcs((const float4*)(edges + (size_t)(e0 + row) * 32 + col));
        }
        const int snd = __ldcs(senders + e0 + lane);
        const int rcv = __ldcs(receivers + e0 + lane);
        const float ivl = g_deg[rcv];
        __syncwarp();

#pragma unroll
        for (int mt = 0; mt < 2; mt++) {
            const int mb = mt * 16;

            // ---- A1 fragments (edge feats, hi/lo split) ----
            uint32_t a1h[2][4], a1l[2][4];
#pragma unroll
            for (int t = 0; t < 2; t++) {
                float2 x0 = *(const float2*)(myE + (mb + r) * 36 + t * 16 + c2x);
                float2 x1 = *(const float2*)(myE + (mb + r + 8) * 36 + t * 16 + c2x);
                float2 x2 = *(const float2*)(myE + (mb + r) * 36 + t * 16 + c2x + 8);
                float2 x3 = *(const float2*)(myE + (mb + r + 8) * 36 + t * 16 + c2x + 8);
                bfs2(x0.x, x0.y, a1h[t][0], a1l[t][0]);
                bfs2(x1.x, x1.y, a1h[t][1], a1l[t][1]);
                bfs2(x2.x, x2.y, a1h[t][2], a1l[t][2]);
                bfs2(x3.x, x3.y, a1h[t][3], a1l[t][3]);
            }

            const int s_r  = __shfl_sync(0xFFFFFFFFu, snd, mb + r);
            const int s_r8 = __shfl_sync(0xFFFFFFFFu, snd, mb + r + 8);
            const int r_r  = __shfl_sync(0xFFFFFFFFu, rcv, mb + r);
            const int r_r8 = __shfl_sync(0xFFFFFFFFu, rcv, mb + r + 8);
            const float* Sr  = g_SR + (size_t)s_r  * 256;
            const float* Sr8 = g_SR + (size_t)s_r8 * 256;
            const float* Rr  = g_SR + (size_t)r_r  * 256 + 128;
            const float* Rr8 = g_SR + (size_t)r_r8 * 256 + 128;

            // ---- GEMM1 + epilogue1 -> A2 frags ----
            uint32_t a2h[8][4], a2l[8][4];
#pragma unroll
            for (int t2 = 0; t2 < 8; t2++) {
                float c1[2][4] = {{0.f, 0.f, 0.f, 0.f}, {0.f, 0.f, 0.f, 0.f}};
#pragma unroll
                for (int half = 0; half < 2; half++) {
                    int j = t2 * 2 + half;
#pragma unroll
                    for (int t = 0; t < 2; t++) {
                        ull bh = sW1f[((j * 2 + t) * 2 + 0) * 32 + lane];
                        ull bl = sW1f[((j * 2 + t) * 2 + 1) * 32 + lane];
                        uint32_t bh0 = (uint32_t)bh, bh1 = (uint32_t)(bh >> 32);
                        uint32_t bl0 = (uint32_t)bl, bl1 = (uint32_t)(bl >> 32);
                        mma16816(c1[half], a1h[t], bh0, bh1);
                        mma16816(c1[half], a1h[t], bl0, bl1);
                        mma16816(c1[half], a1l[t], bh0, bh1);
                    }
                }
#pragma unroll
                for (int half = 0; half < 2; half++) {
                    int j = t2 * 2 + half;
                    float2 sv0 = ldg_keep2(Sr  + j * 8 + c2x, pol);
                    float2 sv1 = ldg_keep2(Sr8 + j * 8 + c2x, pol);
                    float2 rv0 = ldg_keep2(Rr  + j * 8 + c2x, pol);
                    float2 rv1 = ldg_keep2(Rr8 + j * 8 + c2x, pol);
                    float h0 = fmaxf(c1[half][0] + sv0.x + rv0.x, 0.f);
                    float h1 = fmaxf(c1[half][1] + sv0.y + rv0.y, 0.f);
                    float h2 = fmaxf(c1[half][2] + sv1.x + rv1.x, 0.f);
                    float h3 = fmaxf(c1[half][3] + sv1.y + rv1.y, 0.f);
                    bfs2(h0, h1, a2h[t2][half * 2 + 0], a2l[t2][half * 2 + 0]);
                    bfs2(h2, h3, a2h[t2][half * 2 + 1], a2l[t2][half * 2 + 1]);
                }
            }

            const float iv_e = __shfl_sync(0xFFFFFFFFu, ivl, mb + r);
            const float iv_o = __shfl_sync(0xFFFFFFFFu, ivl, mb + r + 8);
            const int   er   = oddl ? r_r8 : r_r;
            const float iv   = oddl ? iv_o : iv_e;
            float* outp = out + (size_t)er * 64 + pb * 4;

            // ---- GEMM2 per n-tile + epilogue2 scatter ----
#pragma unroll
            for (int j = 0; j < 8; j++) {
                float c2[4] = {0.f, 0.f, 0.f, 0.f};
#pragma unroll
                for (int t = 0; t < 8; t++) {
                    ull bh = sW2f[((j * 8 + t) * 2 + 0) * 32 + lane];
                    ull bl = sW2f[((j * 8 + t) * 2 + 1) * 32 + lane];
                    uint32_t bh0 = (uint32_t)bh, bh1 = (uint32_t)(bh >> 32);
                    uint32_t bl0 = (uint32_t)bl, bl1 = (uint32_t)(bl >> 32);
                    mma16816(c2, a2h[t], bh0, bh1);
                    mma16816(c2, a2h[t], bl0, bl1);
                    mma16816(c2, a2l[t], bh0, bh1);
                }
                float x0 = __shfl_xor_sync(0xFFFFFFFFu, c2[0], 1);
                float x1 = __shfl_xor_sync(0xFFFFFFFFu, c2[1], 1);
                float x2 = __shfl_xor_sync(0xFFFFFFFFu, c2[2], 1);
                float x3 = __shfl_xor_sync(0xFFFFFFFFu, c2[3], 1);
                float v0, v1, v2, v3;
                if (!oddl) { v0 = c2[0]; v1 = c2[1]; v2 = x0; v3 = x1; }
                else       { v0 = x2;    v1 = x3;    v2 = c2[2]; v3 = c2[3]; }
                float4 bb = *(const float4*)(b2 + j * 8 + pb * 4);
                v0 = (v0 + bb.x) * iv;  v1 = (v1 + bb.y) * iv;
                v2 = (v2 + bb.z) * iv;  v3 = (v3 + bb.w) * iv;
                asm volatile("red.global.add.v4.f32 [%0], {%1,%2,%3,%4};"
                             :: "l"(outp + j * 8), "f"(v0), "f"(v1), "f"(v2), "f"(v3)
                             : "memory");
            }
        }
    }
}

// ---------------------------------------------------------------------------
// Launch
// ---------------------------------------------------------------------------
extern "C" void kernel_launch(void* const* d_in, const int* in_sizes, int n_in,
                              void* d_out, int out_size)
{
    const float* nodes     = (const float*)d_in[0];
    const float* edges     = (const float*)d_in[1];
    const int*   senders   = (const int*)d_in[2];
    const int*   receivers = (const int*)d_in[3];
    const float* W1        = (const float*)d_in[4];
    const float* b1        = (const float*)d_in[5];
    const float* W2        = (const float*)d_in[6];
    const float* b2        = (const float*)d_in[7];
    const float* Wn        = (const float*)d_in[8];
    const float* bn        = (const float*)d_in[9];
    float* out = (float*)d_out;

    const size_t sm_node = (64 * 68 + 64 * 320) * sizeof(float);          // 99,328 B
    const size_t sm_edge = 16384 + 32768 + 4 * 32 * 36 * sizeof(float);   // 67,584 B

    cudaFuncSetAttribute(node_kernel,
                         cudaFuncAttributeMaxDynamicSharedMemorySize, (int)sm_node);
    cudaFuncSetAttribute(edge_kernel,
                         cudaFuncAttributeMaxDynamicSharedMemorySize, (int)sm_edge);

    init_kernel<<<(NN + 255) / 256, 256>>>(W1, W2);
    deg_kernel_v4<<<(NE / 4 + 255) / 256, 256>>>(receivers);

    int gnodes = (NN + 63) / 64;
    node_kernel<<<gnodes, 256, sm_node>>>(nodes, W1, Wn, b1, bn, out, NN);

    edge_kernel<<<304, 128, sm_edge>>>(edges, senders, receivers, b2, out);
}

// round 13
// speedup vs baseline: 2.1617x; 1.2165x over previous
#include <cuda_runtime.h>
#include <cuda_bf16.h>
#include <cuda_fp16.h>
#include <cstdint>

#define NN 100000
#define NE 1600000

typedef unsigned long long ull;

// ---------------------------------------------------------------------------
// Device scratch (no runtime allocation allowed)
// ---------------------------------------------------------------------------
__device__ __half g_SRh[(size_t)NN * 256]; // fp16: [n][0:128]=S(+b1), [128:256]=R  (51.2 MB)
__device__ float g_deg[NN];                // degree, then 1/max(deg,1)
__device__ ull   g_W1f[16 * 2 * 2 * 32];   // B1 frags: [j16][t2][term2][lane32]
__device__ ull   g_W2f[8 * 8 * 2 * 32];    // B2 frags: [j8][t8][term2][lane32]

// ---------------------------------------------------------------------------
// helpers
// ---------------------------------------------------------------------------
__device__ __forceinline__ void mma16816(float c[4], const uint32_t a[4],
                                         uint32_t b0, uint32_t b1) {
    asm volatile(
        "mma.sync.aligned.m16n8k16.row.col.f32.bf16.bf16.f32 "
        "{%0,%1,%2,%3},{%4,%5,%6,%7},{%8,%9},{%0,%1,%2,%3};"
        : "+f"(c[0]), "+f"(c[1]), "+f"(c[2]), "+f"(c[3])
        : "r"(a[0]), "r"(a[1]), "r"(a[2]), "r"(a[3]), "r"(b0), "r"(b1));
}

// pack (x -> low half, y -> high half) as bf16x2; also produce residual pack
__device__ __forceinline__ void bfs2(float x, float y, uint32_t& hi, uint32_t& lo) {
    asm("cvt.rn.bf16x2.f32 %0, %1, %2;" : "=r"(hi) : "f"(y), "f"(x));
    float xr = x - __uint_as_float(hi << 16);
    float yr = y - __uint_as_float(hi & 0xFFFF0000u);
    asm("cvt.rn.bf16x2.f32 %0, %1, %2;" : "=r"(lo) : "f"(yr), "f"(xr));
}

// fp32x2 helpers for node-side kernels
__device__ __forceinline__ ull dup2(float x) { ull r; asm("mov.b64 %0,{%1,%1};" : "=l"(r) : "f"(x)); return r; }
__device__ __forceinline__ float2 up2(ull v) { float2 r; asm("mov.b64 {%0,%1},%2;" : "=f"(r.x), "=f"(r.y) : "l"(v)); return r; }
__device__ __forceinline__ ull fma2(ull a, ull b, ull c) { ull d; asm("fma.rn.f32x2 %0,%1,%2,%3;" : "=l"(d) : "l"(a), "l"(b), "l"(c)); return d; }

// L2 residency helpers
__device__ __forceinline__ ull mkpol_last() {
    ull p;
    asm("createpolicy.fractional.L2::evict_last.b64 %0, 1.0;" : "=l"(p));
    return p;
}
// load half2 (4B) with evict_last, convert to float2
__device__ __forceinline__ float2 ldg_keep_h2(const __half* p, ull pol) {
    uint32_t v;
    asm volatile("ld.global.nc.L2::cache_hint.b32 %0, [%1], %2;"
                 : "=r"(v) : "l"(p), "l"(pol));
    return __half22float2(*(__half2*)&v);
}
// store 4 halfs (8B) with evict_last
__device__ __forceinline__ void stg_keep_h4(__half* p, uint32_t v0, uint32_t v1, ull pol) {
    asm volatile("st.global.L2::cache_hint.v2.b32 [%0], {%1,%2}, %3;"
                 :: "l"(p), "r"(v0), "r"(v1), "l"(pol) : "memory");
}

// ---------------------------------------------------------------------------
// Merged init kernel: zero g_deg + build weight fragments
// ---------------------------------------------------------------------------
__global__ void init_kernel(const float* __restrict__ W1, const float* __restrict__ W2) {
    int idx = blockIdx.x * blockDim.x + threadIdx.x;
    if (idx < NN) g_deg[idx] = 0.0f;
    if (idx < 2048) {                        // W1c frags
        int lane = idx & 31, fragid = idx >> 5;
        int term = fragid & 1, t = (fragid >> 1) & 1, j = fragid >> 2;
        int n = j * 8 + (lane >> 2);
        int k0 = t * 16 + (lane & 3) * 2;
        float v00 = W1[(size_t)(128 + k0) * 128 + n];
        float v01 = W1[(size_t)(128 + k0 + 1) * 128 + n];
        float v10 = W1[(size_t)(128 + k0 + 8) * 128 + n];
        float v11 = W1[(size_t)(128 + k0 + 9) * 128 + n];
        uint32_t h0, l0, h1, l1;
        bfs2(v00, v01, h0, l0);
        bfs2(v10, v11, h1, l1);
        g_W1f[idx] = term ? (((ull)l1 << 32) | l0) : (((ull)h1 << 32) | h0);
    }
    if (idx < 4096) {                        // W2 frags
        int lane = idx & 31, fragid = idx >> 5;
        int term = fragid & 1, t = (fragid >> 1) & 7, j = fragid >> 4;
        int n = j * 8 + (lane >> 2);
        int k0 = t * 16 + (lane & 3) * 2;
        float v00 = W2[(size_t)k0 * 64 + n];
        float v01 = W2[(size_t)(k0 + 1) * 64 + n];
        float v10 = W2[(size_t)(k0 + 8) * 64 + n];
        float v11 = W2[(size_t)(k0 + 9) * 64 + n];
        uint32_t h0, l0, h1, l1;
        bfs2(v00, v01, h0, l0);
        bfs2(v10, v11, h1, l1);
        g_W2f[idx] = term ? (((ull)l1 << 32) | l0) : (((ull)h1 << 32) | h0);
    }
}

// ---------------------------------------------------------------------------
// Vectorized degree kernel: int4 loads, 4 REDs per thread
// ---------------------------------------------------------------------------
__global__ void deg_kernel_v4(const int* __restrict__ recv) {
    int i = blockIdx.x * blockDim.x + threadIdx.x;
    if (i < NE / 4) {
        int4 r4 = __ldcs(((const int4*)recv) + i);
        atomicAdd(&g_deg[r4.x], 1.0f);
        atomicAdd(&g_deg[r4.y], 1.0f);
        atomicAdd(&g_deg[r4.z], 1.0f);
        atomicAdd(&g_deg[r4.w], 1.0f);
    }
}

// ---------------------------------------------------------------------------
// Fused node kernel: one pass over nodes computes
//   g_SRh[M,256](fp16) = nodes @ [W1a|W1b] (+b1 on S half)  [L2 evict_last]
//   out[M,64]          = nodes @ Wn + bn
//   g_deg              -> 1/max(deg,1)   (folded in)
// ---------------------------------------------------------------------------
__global__ void __launch_bounds__(256) node_kernel(
    const float* __restrict__ A, const float* __restrict__ W1,
    const float* __restrict__ Wn, const float* __restrict__ b1,
    const float* __restrict__ bn, float* __restrict__ out, int M)
{
    extern __shared__ float sm[];
    float* sAT = sm;               // [64][68]
    float* sB  = sm + 64 * 68;     // [64][320]
    const int tid = threadIdx.x;
    const int n0  = blockIdx.x * 64;
    const ull pol = mkpol_last();

    if (tid < 64 && n0 + tid < M)
        g_deg[n0 + tid] = 1.0f / fmaxf(g_deg[n0 + tid], 1.0f);

#pragma unroll
    for (int j = 0; j < 4; j++) {
        int s = tid + j * 256;
        int row = s >> 4, k0 = (s & 15) << 2, gn = n0 + row;
        float4 v = make_float4(0.f, 0.f, 0.f, 0.f);
        if (gn < M) v = *(const float4*)(A + (size_t)gn * 64 + k0);
        sAT[(k0 + 0) * 68 + row] = v.x; sAT[(k0 + 1) * 68 + row] = v.y;
        sAT[(k0 + 2) * 68 + row] = v.z; sAT[(k0 + 3) * 68 + row] = v.w;
    }
#pragma unroll
    for (int j = 0; j < 20; j++) {
        int s  = tid + j * 256;
        int r  = s / 80;
        int c4 = (s % 80) * 4;
        const float* src;
        if (c4 < 128)       src = W1 + (size_t)r * 128 + c4;
        else if (c4 < 256)  src = W1 + (size_t)(64 + r) * 128 + (c4 - 128);
        else                src = Wn + (size_t)r * 64 + (c4 - 256);
        *(float4*)(sB + r * 320 + c4) = *(const float4*)src;
    }
    __syncthreads();

    const int ty = tid >> 4, tx = tid & 15;
    ull acc[4][5][2];
#pragma unroll
    for (int m = 0; m < 4; m++)
#pragma unroll
        for (int q = 0; q < 5; q++) { acc[m][q][0] = 0ull; acc[m][q][1] = 0ull; }

#pragma unroll 4
    for (int k = 0; k < 64; k++) {
        float4 a = *(const float4*)(sAT + k * 68 + ty * 4);
        ull aa[4] = {dup2(a.x), dup2(a.y), dup2(a.z), dup2(a.w)};
#pragma unroll
        for (int q = 0; q < 5; q++) {
            ulonglong2 b = *(const ulonglong2*)(sB + k * 320 + q * 64 + tx * 4);
#pragma unroll
            for (int m = 0; m < 4; m++) {
                acc[m][q][0] = fma2(aa[m], b.x, acc[m][q][0]);
                acc[m][q][1] = fma2(aa[m], b.y, acc[m][q][1]);
            }
        }
    }
    float4 bq[5];
#pragma unroll
    for (int q = 0; q < 5; q++) {
        if (q < 2)      bq[q] = *(const float4*)(b1 + q * 64 + tx * 4);
        else if (q < 4) bq[q] = make_float4(0.f, 0.f, 0.f, 0.f);
        else            bq[q] = *(const float4*)(bn + tx * 4);
    }
#pragma unroll
    for (int m = 0; m < 4; m++) {
        int gn = n0 + ty * 4 + m;
        if (gn < M) {
#pragma unroll
            for (int q = 0; q < 4; q++) {
                float2 u0 = up2(acc[m][q][0]), u1 = up2(acc[m][q][1]);
                __half2 p0 = __floats2half2_rn(u0.x + bq[q].x, u0.y + bq[q].y);
                __half2 p1 = __floats2half2_rn(u1.x + bq[q].z, u1.y + bq[q].w);
                stg_keep_h4(g_SRh + (size_t)gn * 256 + q * 64 + tx * 4,
                            *(uint32_t*)&p0, *(uint32_t*)&p1, pol);
            }
            float2 u0 = up2(acc[m][4][0]), u1 = up2(acc[m][4][1]);
            *(float4*)(out + (size_t)gn * 64 + tx * 4) =
                make_float4(u0.x + bq[4].x, u0.y + bq[4].y, u1.x + bq[4].z, u1.y + bq[4].w);
        }
    }
}

// ---------------------------------------------------------------------------
// Edge kernel: R7/R12 structure; S/R gathers are fp16 half2 (L2-resident)
// ---------------------------------------------------------------------------
#define N_CHUNKS (NE / 32)

__global__ void __launch_bounds__(128, 2) edge_kernel(
    const float* __restrict__ edges,
    const int*   __restrict__ senders,
    const int*   __restrict__ receivers,
    const float* __restrict__ b2,
    float*       __restrict__ out)
{
    extern __shared__ char smem[];
    ull*   sW1f = (ull*)smem;
    ull*   sW2f = (ull*)(smem + 16384);
    float* sE   = (float*)(smem + 49152);

    const int tid  = threadIdx.x;
    const int w    = tid >> 5;
    const int lane = tid & 31;
    const ull pol  = mkpol_last();

    // stage weight fragments once per block
#pragma unroll
    for (int j = 0; j < 16; j++) sW1f[tid + j * 128] = g_W1f[tid + j * 128];
#pragma unroll
    for (int j = 0; j < 32; j++) sW2f[tid + j * 128] = g_W2f[tid + j * 128];
    __syncthreads();

    float* myE = sE + w * 32 * 36;
    const int gw     = blockIdx.x * 4 + w;
    const int stride = gridDim.x * 4;

    const int r   = lane >> 2;          // 0..7
    const int c2x = (lane & 3) * 2;     // 0,2,4,6
    const int pb  = (lane >> 1) & 1;    // pair base selector
    const bool oddl = lane & 1;

    for (int chunk = gw; chunk < N_CHUNKS; chunk += stride) {
        const int e0 = chunk * 32;
        __syncwarp();
#pragma unroll
        for (int q = 0; q < 8; q++) {
            int row = q * 4 + (lane >> 3);
            int col = (lane & 7) * 4;
            *(float4*)(myE + row * 36 + col) =
                __ldcs((const float4*)(edges + (size_t)(e0 + row) * 32 + col));
        }
        const int snd = __ldcs(senders + e0 + lane);
        const int rcv = __ldcs(receivers + e0 + lane);
        const float ivl = g_deg[rcv];
        __syncwarp();

#pragma unroll
        for (int mt = 0; mt < 2; mt++) {
            const int mb = mt * 16;

            // ---- A1 fragments (edge feats, hi/lo split) ----
            uint32_t a1h[2][4], a1l[2][4];
#pragma unroll
            for (int t = 0; t < 2; t++) {
                float2 x0 = *(const float2*)(myE + (mb + r) * 36 + t * 16 + c2x);
                float2 x1 = *(const float2*)(myE + (mb + r + 8) * 36 + t * 16 + c2x);
                float2 x2 = *(const float2*)(myE + (mb + r) * 36 + t * 16 + c2x + 8);
                float2 x3 = *(const float2*)(myE + (mb + r + 8) * 36 + t * 16 + c2x + 8);
                bfs2(x0.x, x0.y, a1h[t][0], a1l[t][0]);
                bfs2(x1.x, x1.y, a1h[t][1], a1l[t][1]);
                bfs2(x2.x, x2.y, a1h[t][2], a1l[t][2]);
                bfs2(x3.x, x3.y, a1h[t][3], a1l[t][3]);
            }

            const int s_r  = __shfl_sync(0xFFFFFFFFu, snd, mb + r);
            const int s_r8 = __shfl_sync(0xFFFFFFFFu, snd, mb + r + 8);
            const int r_r  = __shfl_sync(0xFFFFFFFFu, rcv, mb + r);
            const int r_r8 = __shfl_sync(0xFFFFFFFFu, rcv, mb + r + 8);
            const __half* Sr  = g_SRh + (size_t)s_r  * 256;
            const __half* Sr8 = g_SRh + (size_t)s_r8 * 256;
            const __half* Rr  = g_SRh + (size_t)r_r  * 256 + 128;
            const __half* Rr8 = g_SRh + (size_t)r_r8 * 256 + 128;

            // ---- GEMM1 + epilogue1 -> A2 frags ----
            uint32_t a2h[8][4], a2l[8][4];
#pragma unroll
            for (int t2 = 0; t2 < 8; t2++) {
                float c1[2][4] = {{0.f, 0.f, 0.f, 0.f}, {0.f, 0.f, 0.f, 0.f}};
#pragma unroll
                for (int half = 0; half < 2; half++) {
                    int j = t2 * 2 + half;
#pragma unroll
                    for (int t = 0; t < 2; t++) {
                        ull bh = sW1f[((j * 2 + t) * 2 + 0) * 32 + lane];
                        ull bl = sW1f[((j * 2 + t) * 2 + 1) * 32 + lane];
                        uint32_t bh0 = (uint32_t)bh, bh1 = (uint32_t)(bh >> 32);
                        uint32_t bl0 = (uint32_t)bl, bl1 = (uint32_t)(bl >> 32);
                        mma16816(c1[half], a1h[t], bh0, bh1);
                        mma16816(c1[half], a1h[t], bl0, bl1);
                        mma16816(c1[half], a1l[t], bh0, bh1);
                    }
                }
#pragma unroll
                for (int half = 0; half < 2; half++) {
                    int j = t2 * 2 + half;
                    float2 sv0 = ldg_keep_h2(Sr  + j * 8 + c2x, pol);
                    float2 sv1 = ldg_keep_h2(Sr8 + j * 8 + c2x, pol);
                    float2 rv0 = ldg_keep_h2(Rr  + j * 8 + c2x, pol);
                    float2 rv1 = ldg_keep_h2(Rr8 + j * 8 + c2x, pol);
                    float h0 = fmaxf(c1[half][0] + sv0.x + rv0.x, 0.f);
                    float h1 = fmaxf(c1[half][1] + sv0.y + rv0.y, 0.f);
                    float h2 = fmaxf(c1[half][2] + sv1.x + rv1.x, 0.f);
                    float h3 = fmaxf(c1[half][3] + sv1.y + rv1.y, 0.f);
                    bfs2(h0, h1, a2h[t2][half * 2 + 0], a2l[t2][half * 2 + 0]);
                    bfs2(h2, h3, a2h[t2][half * 2 + 1], a2l[t2][half * 2 + 1]);
                }
            }

            const float iv_e = __shfl_sync(0xFFFFFFFFu, ivl, mb + r);
            const float iv_o = __shfl_sync(0xFFFFFFFFu, ivl, mb + r + 8);
            const int   er   = oddl ? r_r8 : r_r;
            const float iv   = oddl ? iv_o : iv_e;
            float* outp = out + (size_t)er * 64 + pb * 4;

            // ---- GEMM2 per n-tile + epilogue2 scatter ----
#pragma unroll
            for (int j = 0; j < 8; j++) {
                float c2[4] = {0.f, 0.f, 0.f, 0.f};
#pragma unroll
                for (int t = 0; t < 8; t++) {
                    ull bh = sW2f[((j * 8 + t) * 2 + 0) * 32 + lane];
                    ull bl = sW2f[((j * 8 + t) * 2 + 1) * 32 + lane];
                    uint32_t bh0 = (uint32_t)bh, bh1 = (uint32_t)(bh >> 32);
                    uint32_t bl0 = (uint32_t)bl, bl1 = (uint32_t)(bl >> 32);
                    mma16816(c2, a2h[t], bh0, bh1);
                    mma16816(c2, a2h[t], bl0, bl1);
                    mma16816(c2, a2l[t], bh0, bh1);
                }
                float x0 = __shfl_xor_sync(0xFFFFFFFFu, c2[0], 1);
                float x1 = __shfl_xor_sync(0xFFFFFFFFu, c2[1], 1);
                float x2 = __shfl_xor_sync(0xFFFFFFFFu, c2[2], 1);
                float x3 = __shfl_xor_sync(0xFFFFFFFFu, c2[3], 1);
                float v0, v1, v2, v3;
                if (!oddl) { v0 = c2[0]; v1 = c2[1]; v2 = x0; v3 = x1; }
                else       { v0 = x2;    v1 = x3;    v2 = c2[2]; v3 = c2[3]; }
                float4 bb = *(const float4*)(b2 + j * 8 + pb * 4);
                v0 = (v0 + bb.x) * iv;  v1 = (v1 + bb.y) * iv;
                v2 = (v2 + bb.z) * iv;  v3 = (v3 + bb.w) * iv;
                asm volatile("red.global.add.v4.f32 [%0], {%1,%2,%3,%4};"
                             :: "l"(outp + j * 8), "f"(v0), "f"(v1), "f"(v2), "f"(v3)
                             : "memory");
            }
        }
    }
}

// ---------------------------------------------------------------------------
// Launch
// ---------------------------------------------------------------------------
extern "C" void kernel_launch(void* const* d_in, const int* in_sizes, int n_in,
                              void* d_out, int out_size)
{
    const float* nodes     = (const float*)d_in[0];
    const float* edges     = (const float*)d_in[1];
    const int*   senders   = (const int*)d_in[2];
    const int*   receivers = (const int*)d_in[3];
    const float* W1        = (const float*)d_in[4];
    const float* b1        = (const float*)d_in[5];
    const float* W2        = (const float*)d_in[6];
    const float* b2        = (const float*)d_in[7];
    const float* Wn        = (const float*)d_in[8];
    const float* bn        = (const float*)d_in[9];
    float* out = (float*)d_out;

    const size_t sm_node = (64 * 68 + 64 * 320) * sizeof(float);          // 99,328 B
    const size_t sm_edge = 16384 + 32768 + 4 * 32 * 36 * sizeof(float);   // 67,584 B

    cudaFuncSetAttribute(node_kernel,
                         cudaFuncAttributeMaxDynamicSharedMemorySize, (int)sm_node);
    cudaFuncSetAttribute(edge_kernel,
                         cudaFuncAttributeMaxDynamicSharedMemorySize, (int)sm_edge);

    init_kernel<<<(NN + 255) / 256, 256>>>(W1, W2);
    deg_kernel_v4<<<(NE / 4 + 255) / 256, 256>>>(receivers);

    int gnodes = (NN + 63) / 64;
    node_kernel<<<gnodes, 256, sm_node>>>(nodes, W1, Wn, b1, bn, out, NN);

    edge_kernel<<<304, 128, sm_edge>>>(edges, senders, receivers, b2, out);
}

// round 15
// speedup vs baseline: 2.3516x; 1.0879x over previous
#include <cuda_runtime.h>
#include <cuda_bf16.h>
#include <cuda_fp16.h>
#include <cstdint>

#define NN 100000
#define NE 1600000

typedef unsigned long long ull;

// ---------------------------------------------------------------------------
// Device scratch (no runtime allocation allowed)
// ---------------------------------------------------------------------------
__device__ __half g_SRh[(size_t)NN * 256]; // fp16: [n][0:128]=S(+b1), [128:256]=R  (51.2 MB)
__device__ float g_deg[NN];                // raw degree (counted in node_deg_kernel)
__device__ ull   g_W1f[16 * 2 * 2 * 32];   // B1 frags: [j16][t2][term2][lane32]
__device__ ull   g_W2f[8 * 8 * 2 * 32];    // B2 frags: [j8][t8][term2][lane32]

// ---------------------------------------------------------------------------
// helpers
// ---------------------------------------------------------------------------
__device__ __forceinline__ void mma16816(float c[4], const uint32_t a[4],
                                         uint32_t b0, uint32_t b1) {
    asm volatile(
        "mma.sync.aligned.m16n8k16.row.col.f32.bf16.bf16.f32 "
        "{%0,%1,%2,%3},{%4,%5,%6,%7},{%8,%9},{%0,%1,%2,%3};"
        : "+f"(c[0]), "+f"(c[1]), "+f"(c[2]), "+f"(c[3])
        : "r"(a[0]), "r"(a[1]), "r"(a[2]), "r"(a[3]), "r"(b0), "r"(b1));
}

// pack (x -> low half, y -> high half) as bf16x2; also produce residual pack
__device__ __forceinline__ void bfs2(float x, float y, uint32_t& hi, uint32_t& lo) {
    asm("cvt.rn.bf16x2.f32 %0, %1, %2;" : "=r"(hi) : "f"(y), "f"(x));
    float xr = x - __uint_as_float(hi << 16);
    float yr = y - __uint_as_float(hi & 0xFFFF0000u);
    asm("cvt.rn.bf16x2.f32 %0, %1, %2;" : "=r"(lo) : "f"(yr), "f"(xr));
}
// hi-only pack (no residual)
__device__ __forceinline__ uint32_t bfpack2(float x, float y) {
    uint32_t h;
    asm("cvt.rn.bf16x2.f32 %0, %1, %2;" : "=r"(h) : "f"(y), "f"(x));
    return h;
}

// fp32x2 helpers for node-side kernels
__device__ __forceinline__ ull dup2(float x) { ull r; asm("mov.b64 %0,{%1,%1};" : "=l"(r) : "f"(x)); return r; }
__device__ __forceinline__ float2 up2(ull v) { float2 r; asm("mov.b64 {%0,%1},%2;" : "=f"(r.x), "=f"(r.y) : "l"(v)); return r; }
__device__ __forceinline__ ull fma2(ull a, ull b, ull c) { ull d; asm("fma.rn.f32x2 %0,%1,%2,%3;" : "=l"(d) : "l"(a), "l"(b), "l"(c)); return d; }

// L2 residency helpers
__device__ __forceinline__ ull mkpol_last() {
    ull p;
    asm("createpolicy.fractional.L2::evict_last.b64 %0, 1.0;" : "=l"(p));
    return p;
}
// load half2 (4B) with evict_last, convert to float2
__device__ __forceinline__ float2 ldg_keep_h2(const __half* p, ull pol) {
    uint32_t v;
    asm volatile("ld.global.nc.L2::cache_hint.b32 %0, [%1], %2;"
                 : "=r"(v) : "l"(p), "l"(pol));
    return __half22float2(*(__half2*)&v);
}
// store 4 halfs (8B) with evict_last
__device__ __forceinline__ void stg_keep_h4(__half* p, uint32_t v0, uint32_t v1, ull pol) {
    asm volatile("st.global.L2::cache_hint.v2.b32 [%0], {%1,%2}, %3;"
                 :: "l"(p), "r"(v0), "r"(v1), "l"(pol) : "memory");
}

// ---------------------------------------------------------------------------
// Merged init kernel: zero g_deg + build weight fragments
// ---------------------------------------------------------------------------
__global__ void init_kernel(const float* __restrict__ W1, const float* __restrict__ W2) {
    int idx = blockIdx.x * blockDim.x + threadIdx.x;
    if (idx < NN) g_deg[idx] = 0.0f;
    if (idx < 2048) {                        // W1c frags
        int lane = idx & 31, fragid = idx >> 5;
        int term = fragid & 1, t = (fragid >> 1) & 1, j = fragid >> 2;
        int n = j * 8 + (lane >> 2);
        int k0 = t * 16 + (lane & 3) * 2;
        float v00 = W1[(size_t)(128 + k0) * 128 + n];
        float v01 = W1[(size_t)(128 + k0 + 1) * 128 + n];
        float v10 = W1[(size_t)(128 + k0 + 8) * 128 + n];
        float v11 = W1[(size_t)(128 + k0 + 9) * 128 + n];
        uint32_t h0, l0, h1, l1;
        bfs2(v00, v01, h0, l0);
        bfs2(v10, v11, h1, l1);
        g_W1f[idx] = term ? (((ull)l1 << 32) | l0) : (((ull)h1 << 32) | h0);
    }
    if (idx < 4096) {                        // W2 frags
        int lane = idx & 31, fragid = idx >> 5;
        int term = fragid & 1, t = (fragid >> 1) & 7, j = fragid >> 4;
        int n = j * 8 + (lane >> 2);
        int k0 = t * 16 + (lane & 3) * 2;
        float v00 = W2[(size_t)k0 * 64 + n];
        float v01 = W2[(size_t)(k0 + 1) * 64 + n];
        float v10 = W2[(size_t)(k0 + 8) * 64 + n];
        float v11 = W2[(size_t)(k0 + 9) * 64 + n];
        uint32_t h0, l0, h1, l1;
        bfs2(v00, v01, h0, l0);
        bfs2(v10, v11, h1, l1);
        g_W2f[idx] = term ? (((ull)l1 << 32) | l0) : (((ull)h1 << 32) | h0);
    }
}

// ---------------------------------------------------------------------------
// Fused node+degree kernel (single launch, roles by block id):
//   blocks [0, degB):        degree REDs over receivers (int4, grid-stride)
//   blocks [degB, degB+gn):  g_SRh(fp16) = nodes @ [W1a|W1b] (+b1), out = nodes@Wn+bn
// ---------------------------------------------------------------------------
__global__ void __launch_bounds__(256) node_deg_kernel(
    const float* __restrict__ A, const float* __restrict__ W1,
    const float* __restrict__ Wn, const float* __restrict__ b1,
    const float* __restrict__ bn, float* __restrict__ out,
    const int* __restrict__ recv, int degB, int M)
{
    if (blockIdx.x < degB) {
        int i0 = blockIdx.x * blockDim.x + threadIdx.x;
        int stride = degB * blockDim.x;
        for (int i = i0; i < NE / 4; i += stride) {
            int4 r4 = __ldcs(((const int4*)recv) + i);
            atomicAdd(&g_deg[r4.x], 1.0f);
            atomicAdd(&g_deg[r4.y], 1.0f);
            atomicAdd(&g_deg[r4.z], 1.0f);
            atomicAdd(&g_deg[r4.w], 1.0f);
        }
        return;
    }
    const int bx = blockIdx.x - degB;

    extern __shared__ float sm[];
    float* sAT = sm;               // [64][68]
    float* sB  = sm + 64 * 68;     // [64][320]
    const int tid = threadIdx.x;
    const int n0  = bx * 64;
    const ull pol = mkpol_last();

#pragma unroll
    for (int j = 0; j < 4; j++) {
        int s = tid + j * 256;
        int row = s >> 4, k0 = (s & 15) << 2, gn = n0 + row;
        float4 v = make_float4(0.f, 0.f, 0.f, 0.f);
        if (gn < M) v = *(const float4*)(A + (size_t)gn * 64 + k0);
        sAT[(k0 + 0) * 68 + row] = v.x; sAT[(k0 + 1) * 68 + row] = v.y;
        sAT[(k0 + 2) * 68 + row] = v.z; sAT[(k0 + 3) * 68 + row] = v.w;
    }
#pragma unroll
    for (int j = 0; j < 20; j++) {
        int s  = tid + j * 256;
        int r  = s / 80;
        int c4 = (s % 80) * 4;
        const float* src;
        if (c4 < 128)       src = W1 + (size_t)r * 128 + c4;
        else if (c4 < 256)  src = W1 + (size_t)(64 + r) * 128 + (c4 - 128);
        else                src = Wn + (size_t)r * 64 + (c4 - 256);
        *(float4*)(sB + r * 320 + c4) = *(const float4*)src;
    }
    __syncthreads();

    const int ty = tid >> 4, tx = tid & 15;
    ull acc[4][5][2];
#pragma unroll
    for (int m = 0; m < 4; m++)
#pragma unroll
        for (int q = 0; q < 5; q++) { acc[m][q][0] = 0ull; acc[m][q][1] = 0ull; }

#pragma unroll 4
    for (int k = 0; k < 64; k++) {
        float4 a = *(const float4*)(sAT + k * 68 + ty * 4);
        ull aa[4] = {dup2(a.x), dup2(a.y), dup2(a.z), dup2(a.w)};
#pragma unroll
        for (int q = 0; q < 5; q++) {
            ulonglong2 b = *(const ulonglong2*)(sB + k * 320 + q * 64 + tx * 4);
#pragma unroll
            for (int m = 0; m < 4; m++) {
                acc[m][q][0] = fma2(aa[m], b.x, acc[m][q][0]);
                acc[m][q][1] = fma2(aa[m], b.y, acc[m][q][1]);
            }
        }
    }
    float4 bq[5];
#pragma unroll
    for (int q = 0; q < 5; q++) {
        if (q < 2)      bq[q] = *(const float4*)(b1 + q * 64 + tx * 4);
        else if (q < 4) bq[q] = make_float4(0.f, 0.f, 0.f, 0.f);
        else            bq[q] = *(const float4*)(bn + tx * 4);
    }
#pragma unroll
    for (int m = 0; m < 4; m++) {
        int gn = n0 + ty * 4 + m;
        if (gn < M) {
#pragma unroll
            for (int q = 0; q < 4; q++) {
                float2 u0 = up2(acc[m][q][0]), u1 = up2(acc[m][q][1]);
                __half2 p0 = __floats2half2_rn(u0.x + bq[q].x, u0.y + bq[q].y);
                __half2 p1 = __floats2half2_rn(u1.x + bq[q].z, u1.y + bq[q].w);
                stg_keep_h4(g_SRh + (size_t)gn * 256 + q * 64 + tx * 4,
                            *(uint32_t*)&p0, *(uint32_t*)&p1, pol);
            }
            float2 u0 = up2(acc[m][4][0]), u1 = up2(acc[m][4][1]);
            *(float4*)(out + (size_t)gn * 64 + tx * 4) =
                make_float4(u0.x + bq[4].x, u0.y + bq[4].y, u1.x + bq[4].z, u1.y + bq[4].w);
        }
    }
}

// ---------------------------------------------------------------------------
// Edge kernel: R13 structure; GEMM2 uses 2-term split (a2 hi only);
// invdeg computed in-kernel from raw degree.
// ---------------------------------------------------------------------------
#define N_CHUNKS (NE / 32)

__global__ void __launch_bounds__(128, 2) edge_kernel(
    const float* __restrict__ edges,
    const int*   __restrict__ senders,
    const int*   __restrict__ receivers,
    const float* __restrict__ b2,
    float*       __restrict__ out)
{
    extern __shared__ char smem[];
    ull*   sW1f = (ull*)smem;
    ull*   sW2f = (ull*)(smem + 16384);
    float* sE   = (float*)(smem + 49152);

    const int tid  = threadIdx.x;
    const int w    = tid >> 5;
    const int lane = tid & 31;
    const ull pol  = mkpol_last();

    // stage weight fragments once per block
#pragma unroll
    for (int j = 0; j < 16; j++) sW1f[tid + j * 128] = g_W1f[tid + j * 128];
#pragma unroll
    for (int j = 0; j < 32; j++) sW2f[tid + j * 128] = g_W2f[tid + j * 128];
    __syncthreads();

    float* myE = sE + w * 32 * 36;
    const int gw     = blockIdx.x * 4 + w;
    const int stride = gridDim.x * 4;

    const int r   = lane >> 2;          // 0..7
    const int c2x = (lane & 3) * 2;     // 0,2,4,6
    const int pb  = (lane >> 1) & 1;    // pair base selector
    const bool oddl = lane & 1;

    for (int chunk = gw; chunk < N_CHUNKS; chunk += stride) {
        const int e0 = chunk * 32;
        __syncwarp();
#pragma unroll
        for (int q = 0; q < 8; q++) {
            int row = q * 4 + (lane >> 3);
            int col = (lane & 7) * 4;
            *(float4*)(myE + row * 36 + col) =
                __ldcs((const float4*)(edges + (size_t)(e0 + row) * 32 + col));
        }
        const int snd = __ldcs(senders + e0 + lane);
        const int rcv = __ldcs(receivers + e0 + lane);
        const float ivl = 1.0f / fmaxf(g_deg[rcv], 1.0f);
        __syncwarp();

#pragma unroll
        for (int mt = 0; mt < 2; mt++) {
            const int mb = mt * 16;

            // ---- A1 fragments (edge feats, hi/lo split) ----
            uint32_t a1h[2][4], a1l[2][4];
#pragma unroll
            for (int t = 0; t < 2; t++) {
                float2 x0 = *(const float2*)(myE + (mb + r) * 36 + t * 16 + c2x);
                float2 x1 = *(const float2*)(myE + (mb + r + 8) * 36 + t * 16 + c2x);
                float2 x2 = *(const float2*)(myE + (mb + r) * 36 + t * 16 + c2x + 8);
                float2 x3 = *(const float2*)(myE + (mb + r + 8) * 36 + t * 16 + c2x + 8);
                bfs2(x0.x, x0.y, a1h[t][0], a1l[t][0]);
                bfs2(x1.x, x1.y, a1h[t][1], a1l[t][1]);
                bfs2(x2.x, x2.y, a1h[t][2], a1l[t][2]);
                bfs2(x3.x, x3.y, a1h[t][3], a1l[t][3]);
            }

            const int s_r  = __shfl_sync(0xFFFFFFFFu, snd, mb + r);
            const int s_r8 = __shfl_sync(0xFFFFFFFFu, snd, mb + r + 8);
            const int r_r  = __shfl_sync(0xFFFFFFFFu, rcv, mb + r);
            const int r_r8 = __shfl_sync(0xFFFFFFFFu, rcv, mb + r + 8);
            const __half* Sr  = g_SRh + (size_t)s_r  * 256;
            const __half* Sr8 = g_SRh + (size_t)s_r8 * 256;
            const __half* Rr  = g_SRh + (size_t)r_r  * 256 + 128;
            const __half* Rr8 = g_SRh + (size_t)r_r8 * 256 + 128;

            // ---- GEMM1 (3-term) + epilogue1 -> A2 frags (hi only) ----
            uint32_t a2h[8][4];
#pragma unroll
            for (int t2 = 0; t2 < 8; t2++) {
                float c1[2][4] = {{0.f, 0.f, 0.f, 0.f}, {0.f, 0.f, 0.f, 0.f}};
#pragma unroll
                for (int half = 0; half < 2; half++) {
                    int j = t2 * 2 + half;
#pragma unroll
                    for (int t = 0; t < 2; t++) {
                        ull bh = sW1f[((j * 2 + t) * 2 + 0) * 32 + lane];
                        ull bl = sW1f[((j * 2 + t) * 2 + 1) * 32 + lane];
                        uint32_t bh0 = (uint32_t)bh, bh1 = (uint32_t)(bh >> 32);
                        uint32_t bl0 = (uint32_t)bl, bl1 = (uint32_t)(bl >> 32);
                        mma16816(c1[half], a1h[t], bh0, bh1);
                        mma16816(c1[half], a1h[t], bl0, bl1);
                        mma16816(c1[half], a1l[t], bh0, bh1);
                    }
                }
#pragma unroll
                for (int half = 0; half < 2; half++) {
                    int j = t2 * 2 + half;
                    float2 sv0 = ldg_keep_h2(Sr  + j * 8 + c2x, pol);
                    float2 sv1 = ldg_keep_h2(Sr8 + j * 8 + c2x, pol);
                    float2 rv0 = ldg_keep_h2(Rr  + j * 8 + c2x, pol);
                    float2 rv1 = ldg_keep_h2(Rr8 + j * 8 + c2x, pol);
                    float h0 = fmaxf(c1[half][0] + sv0.x + rv0.x, 0.f);
                    float h1 = fmaxf(c1[half][1] + sv0.y + rv0.y, 0.f);
                    float h2 = fmaxf(c1[half][2] + sv1.x + rv1.x, 0.f);
                    float h3 = fmaxf(c1[half][3] + sv1.y + rv1.y, 0.f);
                    a2h[t2][half * 2 + 0] = bfpack2(h0, h1);
                    a2h[t2][half * 2 + 1] = bfpack2(h2, h3);
                }
            }

            const float iv_e = __shfl_sync(0xFFFFFFFFu, ivl, mb + r);
            const float iv_o = __shfl_sync(0xFFFFFFFFu, ivl, mb + r + 8);
            const int   er   = oddl ? r_r8 : r_r;
            const float iv   = oddl ? iv_o : iv_e;
            float* outp = out + (size_t)er * 64 + pb * 4;

            // ---- GEMM2 (2-term: a2h x (W2hi + W2lo)) + epilogue2 scatter ----
#pragma unroll
            for (int j = 0; j < 8; j++) {
                float c2[4] = {0.f, 0.f, 0.f, 0.f};
#pragma unroll
                for (int t = 0; t < 8; t++) {
                    ull bh = sW2f[((j * 8 + t) * 2 + 0) * 32 + lane];
                    ull bl = sW2f[((j * 8 + t) * 2 + 1) * 32 + lane];
                    uint32_t bh0 = (uint32_t)bh, bh1 = (uint32_t)(bh >> 32);
                    uint32_t bl0 = (uint32_t)bl, bl1 = (uint32_t)(bl >> 32);
                    mma16816(c2, a2h[t], bh0, bh1);
                    mma16816(c2, a2h[t], bl0, bl1);
                }
                float x0 = __shfl_xor_sync(0xFFFFFFFFu, c2[0], 1);
                float x1 = __shfl_xor_sync(0xFFFFFFFFu, c2[1], 1);
                float x2 = __shfl_xor_sync(0xFFFFFFFFu, c2[2], 1);
                float x3 = __shfl_xor_sync(0xFFFFFFFFu, c2[3], 1);
                float v0, v1, v2, v3;
                if (!oddl) { v0 = c2[0]; v1 = c2[1]; v2 = x0; v3 = x1; }
                else       { v0 = x2;    v1 = x3;    v2 = c2[2]; v3 = c2[3]; }
                float4 bb = *(const float4*)(b2 + j * 8 + pb * 4);
                v0 = (v0 + bb.x) * iv;  v1 = (v1 + bb.y) * iv;
                v2 = (v2 + bb.z) * iv;  v3 = (v3 + bb.w) * iv;
                asm volatile("red.global.add.v4.f32 [%0], {%1,%2,%3,%4};"
                             :: "l"(outp + j * 8), "f"(v0), "f"(v1), "f"(v2), "f"(v3)
                             : "memory");
            }
        }
    }
}

// ---------------------------------------------------------------------------
// Launch
// ---------------------------------------------------------------------------
extern "C" void kernel_launch(void* const* d_in, const int* in_sizes, int n_in,
                              void* d_out, int out_size)
{
    const float* nodes     = (const float*)d_in[0];
    const float* edges     = (const float*)d_in[1];
    const int*   senders   = (const int*)d_in[2];
    const int*   receivers = (const int*)d_in[3];
    const float* W1        = (const float*)d_in[4];
    const float* b1        = (const float*)d_in[5];
    const float* W2        = (const float*)d_in[6];
    const float* b2        = (const float*)d_in[7];
    const float* Wn        = (const float*)d_in[8];
    const float* bn        = (const float*)d_in[9];
    float* out = (float*)d_out;

    const size_t sm_node = (64 * 68 + 64 * 320) * sizeof(float);   // 99,328 B
    const size_t sm_edge = 16384 + 32768 + 4 * 32 * 36 * sizeof(float);  // 67,584 B

    cudaFuncSetAttribute(node_deg_kernel,
                         cudaFuncAttributeMaxDynamicSharedMemorySize, (int)sm_node);
    cudaFuncSetAttribute(edge_kernel,
                         cudaFuncAttributeMaxDynamicSharedMemorySize, (int)sm_edge);

    init_kernel<<<(NN + 255) / 256, 256>>>(W1, W2);

    const int DEGB = 512;
    int gnodes = (NN + 63) / 64;
    node_deg_kernel<<<DEGB + gnodes, 256, sm_node>>>(
        nodes, W1, Wn, b1, bn, out, receivers, DEGB, NN);

    edge_kernel<<<304, 128, sm_edge>>>(edges, senders, receivers, b2, out);
}